// round 5
// baseline (speedup 1.0000x reference)
#include <cuda_runtime.h>
#include <cuda_bf16.h>
#include <cstdint>

#define BB 4
#define HH 16
#define SS 2048
#define DD 64

#define TM 64          // q rows per CTA
#define KT 64          // keys per tile
#define NTILES (SS / KT)
#define NTHREADS 256
#define KST 72         // smem row stride in halves (144B): conflict-free frag loads

// dynamic smem layout (bytes)
#define TILE_B   (KT * KST * 2)            // 9216
#define BUF_B    (4 * TILE_B)              // Khi,Klo,Vhi,Vlo = 36864
#define ZBUF_OFF (2 * BUF_B)               // 73728, 2*64 floats
#define INVZ_OFF (ZBUF_OFF + 512)
#define SMEM_TOTAL (INVZ_OFF + 256 + 64)

__device__ float g_zinv[BB * HH * SS];

// ---------------- fast 2^y, FFMA only, rel err ~3e-5 ----------------
__device__ __forceinline__ float fexp2f(float y) {
    float t = y + 12582912.0f;               // round-to-int via 1.5*2^23
    int   i = __float_as_int(t) << 23;
    float f = y - (t - 12582912.0f);
    float r = 9.6715857e-3f;
    r = fmaf(r, f, 5.5503714e-2f);
    r = fmaf(r, f, 2.4015310e-1f);
    r = fmaf(r, f, 6.9315315e-1f);
    r = fmaf(r, f, 1.0f);
    return __int_as_float(__float_as_int(r) + i);
}
#define L2E  1.4426950408889634f
#define SHL2 11.541560327111707f   // 8*log2(e):  exp(s-8) = 2^(s*L2E - SHL2)

// ---------------- mma / ldmatrix wrappers ----------------
__device__ __forceinline__ void mma16816(float* c, const uint32_t* a, uint32_t b0, uint32_t b1) {
    asm volatile(
        "mma.sync.aligned.m16n8k16.row.col.f32.bf16.bf16.f32 "
        "{%0,%1,%2,%3},{%4,%5,%6,%7},{%8,%9},{%0,%1,%2,%3};"
        : "+f"(c[0]), "+f"(c[1]), "+f"(c[2]), "+f"(c[3])
        : "r"(a[0]), "r"(a[1]), "r"(a[2]), "r"(a[3]), "r"(b0), "r"(b1));
}
__device__ __forceinline__ void ldsm_x2_trans(uint32_t& r0, uint32_t& r1, uint32_t addr) {
    asm volatile("ldmatrix.sync.aligned.m8n8.x2.trans.shared.b16 {%0,%1}, [%2];"
                 : "=r"(r0), "=r"(r1) : "r"(addr));
}
__device__ __forceinline__ uint32_t pack_bf16(float x, float y) {
    __nv_bfloat162 h = __floats2bfloat162_rn(x, y);
    return *(uint32_t*)&h;
}
__device__ __forceinline__ float bf_hi(uint32_t p) { return __bfloat162float(((__nv_bfloat162*)&p)->x); }
__device__ __forceinline__ float bf_lo(uint32_t p) { return __bfloat162float(((__nv_bfloat162*)&p)->y); }

// load 1/4 of a 64x64 f32 tile into 4 float4 regs (coalesced)
__device__ __forceinline__ void ldg4(float4* r, const float* src, int tid) {
    const float4* g = (const float4*)src;
    #pragma unroll
    for (int it = 0; it < 4; ++it) r[it] = g[tid + it * NTHREADS];
}
// convert regs -> bf16 hi/lo smem (stride KST halves)
__device__ __forceinline__ void cvt_sts(uint16_t* hi, uint16_t* lo, const float4* x, int tid) {
    #pragma unroll
    for (int it = 0; it < 4; ++it) {
        int idx = tid + it * NTHREADS;
        int key = idx >> 4;
        int d4  = (idx & 15) << 2;
        float4 v = x[it];
        uint32_t h01 = pack_bf16(v.x, v.y);
        uint32_t h23 = pack_bf16(v.z, v.w);
        uint32_t l01 = pack_bf16(v.x - bf_hi(h01), v.y - bf_lo(h01));
        uint32_t l23 = pack_bf16(v.z - bf_hi(h23), v.w - bf_lo(h23));
        *(uint2*)(hi + key * KST + d4) = make_uint2(h01, h23);
        *(uint2*)(lo + key * KST + d4) = make_uint2(l01, l23);
    }
}

__global__ __launch_bounds__(NTHREADS, 1)
void psdpa_mma_kernel(const float* __restrict__ q,
                      const float* __restrict__ k,
                      const float* __restrict__ v,
                      const int* __restrict__ mask,
                      float* __restrict__ out,
                      float* __restrict__ attn)
{
    extern __shared__ __align__(16) char dsm[];
    uint16_t* KHI[2] = {(uint16_t*)(dsm),              (uint16_t*)(dsm + BUF_B)};
    uint16_t* KLO[2] = {(uint16_t*)(dsm + TILE_B),     (uint16_t*)(dsm + BUF_B + TILE_B)};
    uint16_t* VHI[2] = {(uint16_t*)(dsm + 2 * TILE_B), (uint16_t*)(dsm + BUF_B + 2 * TILE_B)};
    uint16_t* VLO[2] = {(uint16_t*)(dsm + 3 * TILE_B), (uint16_t*)(dsm + BUF_B + 3 * TILE_B)};
    float* Zbuf  = (float*)(dsm + ZBUF_OFF);
    float* invZs = (float*)(dsm + INVZ_OFF);

    const int tid  = threadIdx.x;
    const int w    = tid >> 5;
    const int lane = tid & 31;
    const int wr   = w & 3;        // row group (16 rows each)
    const int wc   = w >> 2;       // key-column half (32 keys each)
    const int g    = lane >> 2;
    const int j2   = (lane & 3) << 1;

    const int bh = blockIdx.y;
    const int b  = bh >> 4;
    const int q0 = blockIdx.x * TM;

    const float* qbase = q + ((size_t)bh * SS + q0) * DD;
    const float* kbase = k + (size_t)bh * SS * DD;
    const float* vbase = v + (size_t)bh * SS * DD;

    // ---- Q fragments (scaled 1/8), hi/lo split; f32 staging in buffer-1 region ----
    uint32_t qhi[4][4], qlo[4][4];
    {
        float* Qtmp = (float*)KHI[1];     // 16 KB, free until iter-0 staging
        const float4* qg = (const float4*)qbase;
        #pragma unroll
        for (int it = 0; it < 4; ++it) {
            int idx = tid + it * NTHREADS;
            int row = idx >> 4;
            int d4  = (idx & 15) << 2;
            float4 x = qg[idx];
            x.x *= 0.125f; x.y *= 0.125f; x.z *= 0.125f; x.w *= 0.125f;
            *(float4*)(Qtmp + row * DD + d4) = x;
        }
        __syncthreads();
        const int r0 = wr * 16 + g, r1 = r0 + 8;
        #pragma unroll
        for (int ks = 0; ks < 4; ++ks) {
            int d0 = ks * 16 + j2, d1 = d0 + 8;
            float2 x0 = *(float2*)(Qtmp + r0 * DD + d0);
            float2 x1 = *(float2*)(Qtmp + r1 * DD + d0);
            float2 x2 = *(float2*)(Qtmp + r0 * DD + d1);
            float2 x3 = *(float2*)(Qtmp + r1 * DD + d1);
            qhi[ks][0] = pack_bf16(x0.x, x0.y);
            qhi[ks][1] = pack_bf16(x1.x, x1.y);
            qhi[ks][2] = pack_bf16(x2.x, x2.y);
            qhi[ks][3] = pack_bf16(x3.x, x3.y);
            qlo[ks][0] = pack_bf16(x0.x - bf_hi(qhi[ks][0]), x0.y - bf_lo(qhi[ks][0]));
            qlo[ks][1] = pack_bf16(x1.x - bf_hi(qhi[ks][1]), x1.y - bf_lo(qhi[ks][1]));
            qlo[ks][2] = pack_bf16(x2.x - bf_hi(qhi[ks][2]), x2.y - bf_lo(qhi[ks][2]));
            qlo[ks][3] = pack_bf16(x3.x - bf_hi(qhi[ks][3]), x3.y - bf_lo(qhi[ks][3]));
        }
    }

    const int qrow0 = q0 + wr * 16 + g;
    const int qrow8 = qrow0 + 8;
    const int* mrow0 = mask + ((size_t)b * SS + qrow0) * SS;
    const int* mrow8 = mask + ((size_t)b * SS + qrow8) * SS;
    float* arow0 = attn + ((size_t)bh * SS + qrow0) * SS;
    float* arow8 = attn + ((size_t)bh * SS + qrow8) * SS;

    const int lkey = lane & 15;
    uint32_t vhiB[2], vloB[2];
    #pragma unroll
    for (int bf = 0; bf < 2; ++bf) {
        vhiB[bf] = (uint32_t)__cvta_generic_to_shared(VHI[bf]) + ((wc * 32 + lkey) * KST) * 2;
        vloB[bf] = (uint32_t)__cvta_generic_to_shared(VLO[bf]) + ((wc * 32 + lkey) * KST) * 2;
    }

    // ---- stage tile 0 into buffer 0 ----
    {
        float4 kx[4], vx[4];
        ldg4(kx, kbase, tid);
        ldg4(vx, vbase, tid);
        cvt_sts(KHI[0], KLO[0], kx, tid);
        cvt_sts(VHI[0], VLO[0], vx, tid);
    }
    __syncthreads();

    float O[8][4];
    #pragma unroll
    for (int i = 0; i < 8; ++i)
        #pragma unroll
        for (int c = 0; c < 4; ++c) O[i][c] = 0.0f;
    float Zp0 = 0.0f, Zp1 = 0.0f;

    for (int t = 0; t < NTILES; ++t) {
        const int cur = t & 1, nxt = cur ^ 1;
        const bool more = (t + 1 < NTILES);

        // prefetch next K tile + this tile's mask
        float4 kx[4];
        if (more) ldg4(kx, kbase + (size_t)(t + 1) * KT * DD, tid);
        int2 m0[4], m8[4];
        #pragma unroll
        for (int gi = 0; gi < 4; ++gi) {
            int cb = t * KT + wc * 32 + gi * 8 + j2;
            m0[gi] = *(const int2*)(mrow0 + cb);
            m8[gi] = *(const int2*)(mrow8 + cb);
        }

        // ---------------- QK^T : S[4 n8][4] over 32 keys ----------------
        float S[4][4];
        #pragma unroll
        for (int i = 0; i < 4; ++i)
            #pragma unroll
            for (int c = 0; c < 4; ++c) S[i][c] = 0.0f;

        const uint16_t* Kh = KHI[cur];
        const uint16_t* Kl = KLO[cur];
        #pragma unroll
        for (int ks = 0; ks < 4; ++ks) {
            uint32_t bh0[4], bh1[4], bl0[4], bl1[4];
            #pragma unroll
            for (int n8 = 0; n8 < 4; ++n8) {
                int key = wc * 32 + n8 * 8 + g;
                int d   = ks * 16 + j2;
                bh0[n8] = *(uint32_t*)(Kh + key * KST + d);
                bh1[n8] = *(uint32_t*)(Kh + key * KST + d + 8);
                bl0[n8] = *(uint32_t*)(Kl + key * KST + d);
                bl1[n8] = *(uint32_t*)(Kl + key * KST + d + 8);
            }
            #pragma unroll
            for (int n8 = 0; n8 < 4; ++n8) mma16816(S[n8], qhi[ks], bh0[n8], bh1[n8]);
            #pragma unroll
            for (int n8 = 0; n8 < 4; ++n8) mma16816(S[n8], qlo[ks], bh0[n8], bh1[n8]);
            #pragma unroll
            for (int n8 = 0; n8 < 4; ++n8) mma16816(S[n8], qhi[ks], bl0[n8], bl1[n8]);
        }

        // stage next K, prefetch next V
        float4 vx[4];
        if (more) {
            cvt_sts(KHI[nxt], KLO[nxt], kx, tid);
            ldg4(vx, vbase + (size_t)(t + 1) * KT * DD, tid);
        }

        // ---------------- mask + exp + attn store + Z + P frags ----------------
        uint32_t phi[2][4], plo[2][4];
        #pragma unroll
        for (int gi = 0; gi < 4; ++gi) {
            int cb = t * KT + wc * 32 + gi * 8 + j2;
            float e0 = (m0[gi].x != 0) ? fexp2f(fmaf(S[gi][0], L2E, -SHL2)) : 0.0f;
            float e1 = (m0[gi].y != 0) ? fexp2f(fmaf(S[gi][1], L2E, -SHL2)) : 0.0f;
            float e2 = (m8[gi].x != 0) ? fexp2f(fmaf(S[gi][2], L2E, -SHL2)) : 0.0f;
            float e3 = (m8[gi].y != 0) ? fexp2f(fmaf(S[gi][3], L2E, -SHL2)) : 0.0f;
            *(float2*)(arow0 + cb) = make_float2(e0, e1);
            *(float2*)(arow8 + cb) = make_float2(e2, e3);
            Zp0 += e0 + e1;
            Zp1 += e2 + e3;
            int kc = gi >> 1, hh = (gi & 1) << 1;
            uint32_t h01 = pack_bf16(e0, e1);
            uint32_t h23 = pack_bf16(e2, e3);
            phi[kc][hh + 0] = h01;
            phi[kc][hh + 1] = h23;
            plo[kc][hh + 0] = pack_bf16(e0 - bf_hi(h01), e1 - bf_lo(h01));
            plo[kc][hh + 1] = pack_bf16(e2 - bf_hi(h23), e3 - bf_lo(h23));
        }

        // ---------------- P @ V : O[8 dn8][4] ----------------
        #pragma unroll
        for (int kc = 0; kc < 2; ++kc) {
            #pragma unroll
            for (int dn8 = 0; dn8 < 8; ++dn8) {
                uint32_t vh0, vh1, vl0, vl1;
                ldsm_x2_trans(vh0, vh1, vhiB[cur] + (kc * 16 * KST + dn8 * 8) * 2);
                ldsm_x2_trans(vl0, vl1, vloB[cur] + (kc * 16 * KST + dn8 * 8) * 2);
                mma16816(O[dn8], phi[kc], vh0, vh1);
                mma16816(O[dn8], plo[kc], vh0, vh1);
                mma16816(O[dn8], phi[kc], vl0, vl1);
            }
        }

        // stage next V
        if (more) cvt_sts(VHI[nxt], VLO[nxt], vx, tid);
        __syncthreads();
    }

    // ---------------- epilogue: Z reduce, O reduce, write out ----------------
    Zp0 += __shfl_xor_sync(0xffffffffu, Zp0, 1);
    Zp0 += __shfl_xor_sync(0xffffffffu, Zp0, 2);
    Zp1 += __shfl_xor_sync(0xffffffffu, Zp1, 1);
    Zp1 += __shfl_xor_sync(0xffffffffu, Zp1, 2);
    if ((lane & 3) == 0) {
        Zbuf[wc * TM + wr * 16 + g]     = Zp0;
        Zbuf[wc * TM + wr * 16 + g + 8] = Zp1;
    }
    __syncthreads();
    if (tid < TM) {
        float iz = 1.0f / (Zbuf[tid] + Zbuf[TM + tid]);
        invZs[tid] = iz;
        g_zinv[(size_t)bh * SS + q0 + tid] = iz;
    }

    float* Obuf = (float*)dsm;    // [64][68] f32 = 17408 B
    const int r0 = wr * 16 + g, r1 = r0 + 8;
    if (wc == 0) {
        #pragma unroll
        for (int dn8 = 0; dn8 < 8; ++dn8) {
            *(float2*)(Obuf + r0 * 68 + dn8 * 8 + j2) = make_float2(O[dn8][0], O[dn8][1]);
            *(float2*)(Obuf + r1 * 68 + dn8 * 8 + j2) = make_float2(O[dn8][2], O[dn8][3]);
        }
    }
    __syncthreads();
    if (wc == 1) {
        #pragma unroll
        for (int dn8 = 0; dn8 < 8; ++dn8) {
            float2* p0 = (float2*)(Obuf + r0 * 68 + dn8 * 8 + j2);
            float2* p1 = (float2*)(Obuf + r1 * 68 + dn8 * 8 + j2);
            float2 a0 = *p0, a1 = *p1;
            a0.x += O[dn8][0]; a0.y += O[dn8][1];
            a1.x += O[dn8][2]; a1.y += O[dn8][3];
            *p0 = a0; *p1 = a1;
        }
    }
    __syncthreads();
    {
        int row = tid >> 2;
        int dq  = (tid & 3) * 16;
        float iz = invZs[row];
        float* orow = out + ((size_t)bh * SS + q0 + row) * DD + dq;
        #pragma unroll
        for (int i = 0; i < 4; ++i) {
            float4 x = *(float4*)(Obuf + row * 68 + dq + i * 4);
            x.x *= iz; x.y *= iz; x.z *= iz; x.w *= iz;
            *(float4*)(orow + i * 4) = x;
        }
    }
}

// kernel 2: attn[row][*] *= zinv[row]
__global__ __launch_bounds__(256)
void attn_norm_kernel(float* __restrict__ attn)
{
    size_t i = (size_t)blockIdx.x * blockDim.x + threadIdx.x;   // float4 index
    float4* a4 = (float4*)attn;
    float iz = __ldg(&g_zinv[i >> 9]);      // 512 float4 per row
    float4 x = a4[i];
    x.x *= iz; x.y *= iz; x.z *= iz; x.w *= iz;
    a4[i] = x;
}

extern "C" void kernel_launch(void* const* d_in, const int* in_sizes, int n_in,
                              void* d_out, int out_size)
{
    const float* q    = (const float*)d_in[0];
    const float* k    = (const float*)d_in[1];
    const float* v    = (const float*)d_in[2];
    const int*   mask = (const int*)d_in[3];

    float* out  = (float*)d_out;
    float* attn = out + (size_t)BB * HH * SS * DD;

    static bool configured = false;
    if (!configured) {
        cudaFuncSetAttribute(psdpa_mma_kernel,
                             cudaFuncAttributeMaxDynamicSharedMemorySize, SMEM_TOTAL);
        configured = true;
    }

    dim3 grid1(SS / TM, BB * HH);
    psdpa_mma_kernel<<<grid1, NTHREADS, SMEM_TOTAL>>>(q, k, v, mask, out, attn);

    size_t n4 = (size_t)BB * HH * SS * SS / 4;
    attn_norm_kernel<<<(unsigned)(n4 / 256), 256>>>(attn);
}

// round 6
// speedup vs baseline: 1.4932x; 1.4932x over previous
#include <cuda_runtime.h>
#include <cuda_bf16.h>
#include <cstdint>

#define BB 4
#define HH 16
#define SS 2048
#define DD 64

#define TM 64          // q rows per CTA
#define KT 64          // keys per tile
#define NTILES (SS / KT)
#define NTHREADS 256
#define KST 72         // smem row stride in halves (144B): conflict-free frag loads

__device__ float g_zinv[BB * HH * SS];   // scratch (allowed: __device__ global)

// ---------------- fast 2^y (FFMA only), rel err ~2e-6 ----------------
__device__ __forceinline__ float fexp2f(float y) {
    float t = y + 12582912.0f;               // round-to-int via 1.5*2^23
    int   i = __float_as_int(t) << 23;
    float f = y - (t - 12582912.0f);
    float r = 1.3333558e-3f;
    r = fmaf(r, f, 9.6181291e-3f);
    r = fmaf(r, f, 5.5504109e-2f);
    r = fmaf(r, f, 2.4022651e-1f);
    r = fmaf(r, f, 6.9314718e-1f);
    r = fmaf(r, f, 1.0f);
    return __int_as_float(__float_as_int(r) + i);
}
#define L2E  1.4426950408889634f
#define SHL2 11.541560327111707f   // 8*log2(e):  exp(s-8) = 2^(s*L2E - SHL2)

// ---------------- mma / ldmatrix wrappers ----------------
__device__ __forceinline__ void mma16816(float* c, const uint32_t* a, uint32_t b0, uint32_t b1) {
    asm volatile(
        "mma.sync.aligned.m16n8k16.row.col.f32.bf16.bf16.f32 "
        "{%0,%1,%2,%3},{%4,%5,%6,%7},{%8,%9},{%0,%1,%2,%3};"
        : "+f"(c[0]), "+f"(c[1]), "+f"(c[2]), "+f"(c[3])
        : "r"(a[0]), "r"(a[1]), "r"(a[2]), "r"(a[3]), "r"(b0), "r"(b1));
}
__device__ __forceinline__ void ldsm_x2_trans(uint32_t& r0, uint32_t& r1, uint32_t addr) {
    asm volatile("ldmatrix.sync.aligned.m8n8.x2.trans.shared.b16 {%0,%1}, [%2];"
                 : "=r"(r0), "=r"(r1) : "r"(addr));
}
__device__ __forceinline__ uint32_t pack_bf16(float x, float y) {
    __nv_bfloat162 h = __floats2bfloat162_rn(x, y);
    return *(uint32_t*)&h;
}
__device__ __forceinline__ float bf_hi(uint32_t p) { return __bfloat162float(((__nv_bfloat162*)&p)->x); }
__device__ __forceinline__ float bf_lo(uint32_t p) { return __bfloat162float(((__nv_bfloat162*)&p)->y); }

// stage [64 keys][64 d] f32 -> bf16 hi/lo smem rows of stride KST halves
__device__ __forceinline__ void stage_bf16(uint16_t* hi, uint16_t* lo,
                                           const float* src, int tid) {
    const float4* g = (const float4*)src;
    #pragma unroll
    for (int it = 0; it < 4; ++it) {
        int idx = tid + it * NTHREADS;
        int key = idx >> 4;
        int d4  = (idx & 15) << 2;
        float4 x = g[idx];
        uint32_t h01 = pack_bf16(x.x, x.y);
        uint32_t h23 = pack_bf16(x.z, x.w);
        uint32_t l01 = pack_bf16(x.x - bf_hi(h01), x.y - bf_lo(h01));
        uint32_t l23 = pack_bf16(x.z - bf_hi(h23), x.w - bf_lo(h23));
        *(uint2*)(hi + key * KST + d4) = make_uint2(h01, h23);
        *(uint2*)(lo + key * KST + d4) = make_uint2(l01, l23);
    }
}

__global__ __launch_bounds__(NTHREADS, 2)
void psdpa_mma_kernel(const float* __restrict__ q,
                      const float* __restrict__ k,
                      const float* __restrict__ v,
                      const int* __restrict__ mask,
                      float* __restrict__ out,
                      float* __restrict__ attn)
{
    __shared__ uint16_t Khi[KT * KST], Klo[KT * KST];
    __shared__ uint16_t Vhi[KT * KST], Vlo[KT * KST];
    __shared__ float Zbuf[2 * TM];
    __shared__ float invZs[TM];

    const int tid  = threadIdx.x;
    const int w    = tid >> 5;
    const int lane = tid & 31;
    const int wr   = w & 3;        // row group (16 rows each)
    const int wc   = w >> 2;       // key-column half (32 keys each)
    const int g    = lane >> 2;
    const int j2   = (lane & 3) << 1;

    const int bh = blockIdx.y;
    const int b  = bh >> 4;
    const int q0 = blockIdx.x * TM;

    const float* qbase = q + ((size_t)bh * SS + q0) * DD;
    const float* kbase = k + (size_t)bh * SS * DD;
    const float* vbase = v + (size_t)bh * SS * DD;

    // ---- Q fragments (scaled 1/8), hi/lo split: reuse V smem as f32 staging ----
    uint32_t qhi[4][4], qlo[4][4];
    {
        float* Qtmp = (float*)Vhi;   // 16 KB fits in Vhi+Vlo (36 KB)
        const float4* qg = (const float4*)qbase;
        #pragma unroll
        for (int it = 0; it < 4; ++it) {
            int idx = tid + it * NTHREADS;
            int row = idx >> 4;
            int d4  = (idx & 15) << 2;
            float4 x = qg[idx];
            x.x *= 0.125f; x.y *= 0.125f; x.z *= 0.125f; x.w *= 0.125f;
            *(float4*)(Qtmp + row * DD + d4) = x;
        }
        __syncthreads();
        const int r0 = wr * 16 + g, r1 = r0 + 8;
        #pragma unroll
        for (int ks = 0; ks < 4; ++ks) {
            int d0 = ks * 16 + j2, d1 = d0 + 8;
            float2 x0 = *(float2*)(Qtmp + r0 * DD + d0);
            float2 x1 = *(float2*)(Qtmp + r1 * DD + d0);
            float2 x2 = *(float2*)(Qtmp + r0 * DD + d1);
            float2 x3 = *(float2*)(Qtmp + r1 * DD + d1);
            qhi[ks][0] = pack_bf16(x0.x, x0.y);
            qhi[ks][1] = pack_bf16(x1.x, x1.y);
            qhi[ks][2] = pack_bf16(x2.x, x2.y);
            qhi[ks][3] = pack_bf16(x3.x, x3.y);
            qlo[ks][0] = pack_bf16(x0.x - bf_hi(qhi[ks][0]), x0.y - bf_lo(qhi[ks][0]));
            qlo[ks][1] = pack_bf16(x1.x - bf_hi(qhi[ks][1]), x1.y - bf_lo(qhi[ks][1]));
            qlo[ks][2] = pack_bf16(x2.x - bf_hi(qhi[ks][2]), x2.y - bf_lo(qhi[ks][2]));
            qlo[ks][3] = pack_bf16(x3.x - bf_hi(qhi[ks][3]), x3.y - bf_lo(qhi[ks][3]));
        }
    }

    const int qrow0 = q0 + wr * 16 + g;
    const int qrow8 = qrow0 + 8;
    const int* mrow0 = mask + ((size_t)b * SS + qrow0) * SS;
    const int* mrow8 = mask + ((size_t)b * SS + qrow8) * SS;
    float* arow0 = attn + ((size_t)bh * SS + qrow0) * SS;
    float* arow8 = attn + ((size_t)bh * SS + qrow8) * SS;

    // ldmatrix per-lane base address into V tiles (row = key, 16B block = 8 d)
    const int lkey = lane & 15;
    const uint32_t vhi_base = (uint32_t)__cvta_generic_to_shared(Vhi) + ((wc * 32 + lkey) * KST) * 2;
    const uint32_t vlo_base = (uint32_t)__cvta_generic_to_shared(Vlo) + ((wc * 32 + lkey) * KST) * 2;

    float O[8][4];
    #pragma unroll
    for (int i = 0; i < 8; ++i)
        #pragma unroll
        for (int c = 0; c < 4; ++c) O[i][c] = 0.0f;
    float Zp0 = 0.0f, Zp1 = 0.0f;

    for (int t = 0; t < NTILES; ++t) {
        __syncthreads();
        stage_bf16(Khi, Klo, kbase + (size_t)t * KT * DD, tid);
        stage_bf16(Vhi, Vlo, vbase + (size_t)t * KT * DD, tid);
        __syncthreads();

        // ---------------- QK^T : S[4 n8][4] over 32 keys ----------------
        float S[4][4];
        #pragma unroll
        for (int i = 0; i < 4; ++i)
            #pragma unroll
            for (int c = 0; c < 4; ++c) S[i][c] = 0.0f;

        #pragma unroll
        for (int ks = 0; ks < 4; ++ks) {
            uint32_t bh0[4], bh1[4], bl0[4], bl1[4];
            #pragma unroll
            for (int n8 = 0; n8 < 4; ++n8) {
                int key = wc * 32 + n8 * 8 + g;
                int d   = ks * 16 + j2;
                bh0[n8] = *(uint32_t*)(Khi + key * KST + d);
                bh1[n8] = *(uint32_t*)(Khi + key * KST + d + 8);
                bl0[n8] = *(uint32_t*)(Klo + key * KST + d);
                bl1[n8] = *(uint32_t*)(Klo + key * KST + d + 8);
            }
            #pragma unroll
            for (int n8 = 0; n8 < 4; ++n8) mma16816(S[n8], qhi[ks], bh0[n8], bh1[n8]);
            #pragma unroll
            for (int n8 = 0; n8 < 4; ++n8) mma16816(S[n8], qlo[ks], bh0[n8], bh1[n8]);
            #pragma unroll
            for (int n8 = 0; n8 < 4; ++n8) mma16816(S[n8], qhi[ks], bl0[n8], bl1[n8]);
        }

        // ---------------- mask + exp + attn store + Z + P frags ----------------
        uint32_t phi[2][4], plo[2][4];
        #pragma unroll
        for (int gi = 0; gi < 4; ++gi) {
            int cb = t * KT + wc * 32 + gi * 8 + j2;
            int2 m0 = *(const int2*)(mrow0 + cb);
            int2 m8 = *(const int2*)(mrow8 + cb);
            float e0 = (m0.x != 0) ? fexp2f(fmaf(S[gi][0], L2E, -SHL2)) : 0.0f;
            float e1 = (m0.y != 0) ? fexp2f(fmaf(S[gi][1], L2E, -SHL2)) : 0.0f;
            float e2 = (m8.x != 0) ? fexp2f(fmaf(S[gi][2], L2E, -SHL2)) : 0.0f;
            float e3 = (m8.y != 0) ? fexp2f(fmaf(S[gi][3], L2E, -SHL2)) : 0.0f;
            *(float2*)(arow0 + cb) = make_float2(e0, e1);
            *(float2*)(arow8 + cb) = make_float2(e2, e3);
            Zp0 += e0 + e1;
            Zp1 += e2 + e3;
            int kc = gi >> 1, hh = (gi & 1) << 1;
            uint32_t h01 = pack_bf16(e0, e1);
            uint32_t h23 = pack_bf16(e2, e3);
            phi[kc][hh + 0] = h01;
            phi[kc][hh + 1] = h23;
            plo[kc][hh + 0] = pack_bf16(e0 - bf_hi(h01), e1 - bf_lo(h01));
            plo[kc][hh + 1] = pack_bf16(e2 - bf_hi(h23), e3 - bf_lo(h23));
        }

        // ---------------- P @ V : O[8 dn8][4] ----------------
        #pragma unroll
        for (int kc = 0; kc < 2; ++kc) {
            #pragma unroll
            for (int dn8 = 0; dn8 < 8; ++dn8) {
                uint32_t vh0, vh1, vl0, vl1;
                ldsm_x2_trans(vh0, vh1, vhi_base + (kc * 16 * KST + dn8 * 8) * 2);
                ldsm_x2_trans(vl0, vl1, vlo_base + (kc * 16 * KST + dn8 * 8) * 2);
                mma16816(O[dn8], phi[kc], vh0, vh1);
                mma16816(O[dn8], plo[kc], vh0, vh1);
                mma16816(O[dn8], phi[kc], vl0, vl1);
            }
        }
    }

    // ---------------- epilogue: Z reduce, O reduce, write out ----------------
    Zp0 += __shfl_xor_sync(0xffffffffu, Zp0, 1);
    Zp0 += __shfl_xor_sync(0xffffffffu, Zp0, 2);
    Zp1 += __shfl_xor_sync(0xffffffffu, Zp1, 1);
    Zp1 += __shfl_xor_sync(0xffffffffu, Zp1, 2);
    __syncthreads();              // all tiles done using smem
    if ((lane & 3) == 0) {
        Zbuf[wc * TM + wr * 16 + g]     = Zp0;
        Zbuf[wc * TM + wr * 16 + g + 8] = Zp1;
    }
    __syncthreads();
    if (tid < TM) {
        float iz = 1.0f / (Zbuf[tid] + Zbuf[TM + tid]);
        invZs[tid] = iz;
        g_zinv[(size_t)bh * SS + q0 + tid] = iz;
    }

    float* Obuf = (float*)Khi;    // [64][68] f32 = 17408 B, fits Khi+Klo
    const int r0 = wr * 16 + g, r1 = r0 + 8;
    if (wc == 0) {
        #pragma unroll
        for (int dn8 = 0; dn8 < 8; ++dn8) {
            *(float2*)(Obuf + r0 * 68 + dn8 * 8 + j2) = make_float2(O[dn8][0], O[dn8][1]);
            *(float2*)(Obuf + r1 * 68 + dn8 * 8 + j2) = make_float2(O[dn8][2], O[dn8][3]);
        }
    }
    __syncthreads();
    if (wc == 1) {
        #pragma unroll
        for (int dn8 = 0; dn8 < 8; ++dn8) {
            float2* p0 = (float2*)(Obuf + r0 * 68 + dn8 * 8 + j2);
            float2* p1 = (float2*)(Obuf + r1 * 68 + dn8 * 8 + j2);
            float2 a0 = *p0, a1 = *p1;
            a0.x += O[dn8][0]; a0.y += O[dn8][1];
            a1.x += O[dn8][2]; a1.y += O[dn8][3];
            *p0 = a0; *p1 = a1;
        }
    }
    __syncthreads();
    {
        int row = tid >> 2;
        int dq  = (tid & 3) * 16;
        float iz = invZs[row];
        float* orow = out + ((size_t)bh * SS + q0 + row) * DD + dq;
        #pragma unroll
        for (int i = 0; i < 4; ++i) {
            float4 x = *(float4*)(Obuf + row * 68 + dq + i * 4);
            x.x *= iz; x.y *= iz; x.z *= iz; x.w *= iz;
            *(float4*)(orow + i * 4) = x;
        }
    }
}

// kernel 2: attn[row][*] *= zinv[row]
__global__ __launch_bounds__(256)
void attn_norm_kernel(float* __restrict__ attn)
{
    size_t i = (size_t)blockIdx.x * blockDim.x + threadIdx.x;   // float4 index
    float4* a4 = (float4*)attn;
    float iz = __ldg(&g_zinv[i >> 9]);      // 512 float4 per row
    float4 x = a4[i];
    x.x *= iz; x.y *= iz; x.z *= iz; x.w *= iz;
    a4[i] = x;
}

extern "C" void kernel_launch(void* const* d_in, const int* in_sizes, int n_in,
                              void* d_out, int out_size)
{
    const float* q    = (const float*)d_in[0];
    const float* k    = (const float*)d_in[1];
    const float* v    = (const float*)d_in[2];
    const int*   mask = (const int*)d_in[3];

    float* out  = (float*)d_out;
    float* attn = out + (size_t)BB * HH * SS * DD;

    dim3 grid1(SS / TM, BB * HH);
    psdpa_mma_kernel<<<grid1, NTHREADS>>>(q, k, v, mask, out, attn);

    size_t n4 = (size_t)BB * HH * SS * SS / 4;
    attn_norm_kernel<<<(unsigned)(n4 / 256), 256>>>(attn);
}

// round 7
// speedup vs baseline: 1.5619x; 1.0460x over previous
#include <cuda_runtime.h>
#include <cuda_bf16.h>
#include <cstdint>

#define BB 4
#define HH 16
#define SS 2048
#define DD 64

#define TM 64          // q rows per CTA
#define KT 64          // keys per tile
#define NTILES (SS / KT)
#define NTHREADS 256
#define KST 72         // smem row stride in halves (144B): conflict-free frag loads

#define TILE_B  (KT * KST * 2)     // 9216 bytes per part
#define BUF_B   (4 * TILE_B)       // Khi,Klo,Vhi,Vlo = 36864
#define NBUF 3
#define ZBUF_OFF (NBUF * BUF_B)    // 110592
#define INVZ_OFF (ZBUF_OFF + 512)
#define SMEM_TOTAL (INVZ_OFF + 256)

#define NELEM (BB * HH * SS * DD)  // 8388608

__device__ float g_zinv[BB * HH * SS];
__device__ uint16_t g_khi[NELEM];
__device__ uint16_t g_klo[NELEM];
__device__ uint16_t g_vhi[NELEM];
__device__ uint16_t g_vlo[NELEM];

// ---------------- fast 2^y (FFMA only), rel err ~2e-6 ----------------
__device__ __forceinline__ float fexp2f(float y) {
    float t = y + 12582912.0f;               // round-to-int via 1.5*2^23
    int   i = __float_as_int(t) << 23;
    float f = y - (t - 12582912.0f);
    float r = 1.3333558e-3f;
    r = fmaf(r, f, 9.6181291e-3f);
    r = fmaf(r, f, 5.5504109e-2f);
    r = fmaf(r, f, 2.4022651e-1f);
    r = fmaf(r, f, 6.9314718e-1f);
    r = fmaf(r, f, 1.0f);
    return __int_as_float(__float_as_int(r) + i);
}
#define L2E  1.4426950408889634f
#define SHL2 11.541560327111707f   // 8*log2(e):  exp(s-8) = 2^(s*L2E - SHL2)

// ---------------- wrappers ----------------
__device__ __forceinline__ void mma16816(float* c, const uint32_t* a, uint32_t b0, uint32_t b1) {
    asm volatile(
        "mma.sync.aligned.m16n8k16.row.col.f32.bf16.bf16.f32 "
        "{%0,%1,%2,%3},{%4,%5,%6,%7},{%8,%9},{%0,%1,%2,%3};"
        : "+f"(c[0]), "+f"(c[1]), "+f"(c[2]), "+f"(c[3])
        : "r"(a[0]), "r"(a[1]), "r"(a[2]), "r"(a[3]), "r"(b0), "r"(b1));
}
__device__ __forceinline__ void ldsm_x2_trans(uint32_t& r0, uint32_t& r1, uint32_t addr) {
    asm volatile("ldmatrix.sync.aligned.m8n8.x2.trans.shared.b16 {%0,%1}, [%2];"
                 : "=r"(r0), "=r"(r1) : "r"(addr));
}
__device__ __forceinline__ uint32_t pack_bf16(float x, float y) {
    __nv_bfloat162 h = __floats2bfloat162_rn(x, y);
    return *(uint32_t*)&h;
}
__device__ __forceinline__ float bf_hi(uint32_t p) { return __bfloat162float(((__nv_bfloat162*)&p)->x); }
__device__ __forceinline__ float bf_lo(uint32_t p) { return __bfloat162float(((__nv_bfloat162*)&p)->y); }

__device__ __forceinline__ void cp16(uint32_t dst, const void* src) {
    asm volatile("cp.async.cg.shared.global [%0], [%1], 16;" :: "r"(dst), "l"(src));
}
#define CP_COMMIT() asm volatile("cp.async.commit_group;" ::: "memory")
#define CP_WAIT(n)  asm volatile("cp.async.wait_group %0;" :: "n"(n) : "memory")

// stage one tile (4 parts) via cp.async: 8 x 16B per thread
__device__ __forceinline__ void stage_async(uint32_t sbuf, size_t base, int tid) {
    const uint16_t* srcs[4] = {g_khi + base, g_klo + base, g_vhi + base, g_vlo + base};
    #pragma unroll
    for (int part = 0; part < 4; ++part) {
        uint32_t dpart = sbuf + part * TILE_B;
        #pragma unroll
        for (int it = 0; it < 2; ++it) {
            int idx = tid + it * NTHREADS;     // 0..511
            int row = idx >> 3;
            int seg = idx & 7;
            cp16(dpart + row * 144 + seg * 16, srcs[part] + row * 64 + seg * 8);
        }
    }
}

// ---------------- prepack: f32 K,V -> bf16 hi/lo ----------------
__global__ __launch_bounds__(256)
void prepack_kernel(const float* __restrict__ k, const float* __restrict__ v)
{
    size_t i = (size_t)blockIdx.x * 256 + threadIdx.x;   // float4 index
    float4 x = ((const float4*)k)[i];
    uint32_t h01 = pack_bf16(x.x, x.y);
    uint32_t h23 = pack_bf16(x.z, x.w);
    uint32_t l01 = pack_bf16(x.x - bf_hi(h01), x.y - bf_lo(h01));
    uint32_t l23 = pack_bf16(x.z - bf_hi(h23), x.w - bf_lo(h23));
    ((uint2*)g_khi)[i] = make_uint2(h01, h23);
    ((uint2*)g_klo)[i] = make_uint2(l01, l23);
    float4 y = ((const float4*)v)[i];
    h01 = pack_bf16(y.x, y.y);
    h23 = pack_bf16(y.z, y.w);
    l01 = pack_bf16(y.x - bf_hi(h01), y.y - bf_lo(h01));
    l23 = pack_bf16(y.z - bf_hi(h23), y.w - bf_lo(h23));
    ((uint2*)g_vhi)[i] = make_uint2(h01, h23);
    ((uint2*)g_vlo)[i] = make_uint2(l01, l23);
}

__global__ __launch_bounds__(NTHREADS, 2)
void psdpa_mma_kernel(const float* __restrict__ q,
                      const int* __restrict__ mask,
                      float* __restrict__ out,
                      float* __restrict__ attn)
{
    extern __shared__ __align__(16) char dsm[];
    float* Zbuf  = (float*)(dsm + ZBUF_OFF);
    float* invZs = (float*)(dsm + INVZ_OFF);
    const uint32_t sbase = (uint32_t)__cvta_generic_to_shared(dsm);

    const int tid  = threadIdx.x;
    const int w    = tid >> 5;
    const int lane = tid & 31;
    const int wr   = w & 3;        // row group (16 rows each)
    const int wc   = w >> 2;       // key-column half (32 keys each)
    const int g    = lane >> 2;
    const int j2   = (lane & 3) << 1;

    const int bh = blockIdx.y;
    const int b  = bh >> 4;
    const int q0 = blockIdx.x * TM;

    const float* qbase = q + ((size_t)bh * SS + q0) * DD;
    const size_t kvbase = (size_t)bh * SS * DD;

    // ---- Q fragments (scaled 1/8), hi/lo split; f32 staging in buffer region ----
    uint32_t qhi[4][4], qlo[4][4];
    {
        float* Qtmp = (float*)dsm;   // 16 KB
        const float4* qg = (const float4*)qbase;
        #pragma unroll
        for (int it = 0; it < 4; ++it) {
            int idx = tid + it * NTHREADS;
            int row = idx >> 4;
            int d4  = (idx & 15) << 2;
            float4 x = qg[idx];
            x.x *= 0.125f; x.y *= 0.125f; x.z *= 0.125f; x.w *= 0.125f;
            *(float4*)(Qtmp + row * DD + d4) = x;
        }
        __syncthreads();
        const int r0 = wr * 16 + g, r1 = r0 + 8;
        #pragma unroll
        for (int ks = 0; ks < 4; ++ks) {
            int d0 = ks * 16 + j2, d1 = d0 + 8;
            float2 x0 = *(float2*)(Qtmp + r0 * DD + d0);
            float2 x1 = *(float2*)(Qtmp + r1 * DD + d0);
            float2 x2 = *(float2*)(Qtmp + r0 * DD + d1);
            float2 x3 = *(float2*)(Qtmp + r1 * DD + d1);
            qhi[ks][0] = pack_bf16(x0.x, x0.y);
            qhi[ks][1] = pack_bf16(x1.x, x1.y);
            qhi[ks][2] = pack_bf16(x2.x, x2.y);
            qhi[ks][3] = pack_bf16(x3.x, x3.y);
            qlo[ks][0] = pack_bf16(x0.x - bf_hi(qhi[ks][0]), x0.y - bf_lo(qhi[ks][0]));
            qlo[ks][1] = pack_bf16(x1.x - bf_hi(qhi[ks][1]), x1.y - bf_lo(qhi[ks][1]));
            qlo[ks][2] = pack_bf16(x2.x - bf_hi(qhi[ks][2]), x2.y - bf_lo(qhi[ks][2]));
            qlo[ks][3] = pack_bf16(x3.x - bf_hi(qhi[ks][3]), x3.y - bf_lo(qhi[ks][3]));
        }
        __syncthreads();   // Qtmp region free before cp.async writes
    }

    const int qrow0 = q0 + wr * 16 + g;
    const int qrow8 = qrow0 + 8;
    const int* mrow0 = mask + ((size_t)b * SS + qrow0) * SS;
    const int* mrow8 = mask + ((size_t)b * SS + qrow8) * SS;
    float* arow0 = attn + ((size_t)bh * SS + qrow0) * SS;
    float* arow8 = attn + ((size_t)bh * SS + qrow8) * SS;

    const int lkey = lane & 15;
    const uint32_t vfrag_off = ((wc * 32 + lkey) * KST) * 2;   // within a part

    // ---- prologue: issue tiles 0 and 1 ----
    stage_async(sbase + 0 * BUF_B, kvbase + 0 * (size_t)KT * DD, tid);
    CP_COMMIT();
    stage_async(sbase + 1 * BUF_B, kvbase + 1 * (size_t)KT * DD, tid);
    CP_COMMIT();

    float O[8][4];
    #pragma unroll
    for (int i = 0; i < 8; ++i)
        #pragma unroll
        for (int c = 0; c < 4; ++c) O[i][c] = 0.0f;
    float Zp0 = 0.0f, Zp1 = 0.0f;

    int cur = 0;
    for (int t = 0; t < NTILES; ++t) {
        if (t + 1 < NTILES) { CP_WAIT(1); } else { CP_WAIT(0); }
        __syncthreads();
        if (t + 2 < NTILES) {
            int nb = cur + 2; if (nb >= NBUF) nb -= NBUF;
            stage_async(sbase + nb * BUF_B, kvbase + (size_t)(t + 2) * KT * DD, tid);
            CP_COMMIT();
        }

        const uint16_t* Khi = (const uint16_t*)(dsm + cur * BUF_B);
        const uint16_t* Klo = (const uint16_t*)(dsm + cur * BUF_B + TILE_B);
        const uint32_t vhi_base = sbase + cur * BUF_B + 2 * TILE_B + vfrag_off;
        const uint32_t vlo_base = sbase + cur * BUF_B + 3 * TILE_B + vfrag_off;

        // ---------------- QK^T : S[4 n8][4] over 32 keys ----------------
        float S[4][4];
        #pragma unroll
        for (int i = 0; i < 4; ++i)
            #pragma unroll
            for (int c = 0; c < 4; ++c) S[i][c] = 0.0f;

        #pragma unroll
        for (int ks = 0; ks < 4; ++ks) {
            uint32_t bh0[4], bh1[4], bl0[4], bl1[4];
            #pragma unroll
            for (int n8 = 0; n8 < 4; ++n8) {
                int key = wc * 32 + n8 * 8 + g;
                int d   = ks * 16 + j2;
                bh0[n8] = *(uint32_t*)(Khi + key * KST + d);
                bh1[n8] = *(uint32_t*)(Khi + key * KST + d + 8);
                bl0[n8] = *(uint32_t*)(Klo + key * KST + d);
                bl1[n8] = *(uint32_t*)(Klo + key * KST + d + 8);
            }
            #pragma unroll
            for (int n8 = 0; n8 < 4; ++n8) mma16816(S[n8], qhi[ks], bh0[n8], bh1[n8]);
            #pragma unroll
            for (int n8 = 0; n8 < 4; ++n8) mma16816(S[n8], qlo[ks], bh0[n8], bh1[n8]);
            #pragma unroll
            for (int n8 = 0; n8 < 4; ++n8) mma16816(S[n8], qhi[ks], bl0[n8], bl1[n8]);
        }

        // ---------------- mask + exp + attn store + Z + P frags ----------------
        uint32_t phi[2][4], plo[2][4];
        #pragma unroll
        for (int gi = 0; gi < 4; ++gi) {
            int cb = t * KT + wc * 32 + gi * 8 + j2;
            int2 m0 = *(const int2*)(mrow0 + cb);
            int2 m8 = *(const int2*)(mrow8 + cb);
            float e0 = (m0.x != 0) ? fexp2f(fmaf(S[gi][0], L2E, -SHL2)) : 0.0f;
            float e1 = (m0.y != 0) ? fexp2f(fmaf(S[gi][1], L2E, -SHL2)) : 0.0f;
            float e2 = (m8.x != 0) ? fexp2f(fmaf(S[gi][2], L2E, -SHL2)) : 0.0f;
            float e3 = (m8.y != 0) ? fexp2f(fmaf(S[gi][3], L2E, -SHL2)) : 0.0f;
            *(float2*)(arow0 + cb) = make_float2(e0, e1);
            *(float2*)(arow8 + cb) = make_float2(e2, e3);
            Zp0 += e0 + e1;
            Zp1 += e2 + e3;
            int kc = gi >> 1, hh = (gi & 1) << 1;
            uint32_t h01 = pack_bf16(e0, e1);
            uint32_t h23 = pack_bf16(e2, e3);
            phi[kc][hh + 0] = h01;
            phi[kc][hh + 1] = h23;
            plo[kc][hh + 0] = pack_bf16(e0 - bf_hi(h01), e1 - bf_lo(h01));
            plo[kc][hh + 1] = pack_bf16(e2 - bf_hi(h23), e3 - bf_lo(h23));
        }

        // ---------------- P @ V : O[8 dn8][4] ----------------
        #pragma unroll
        for (int kc = 0; kc < 2; ++kc) {
            #pragma unroll
            for (int dn8 = 0; dn8 < 8; ++dn8) {
                uint32_t vh0, vh1, vl0, vl1;
                ldsm_x2_trans(vh0, vh1, vhi_base + (kc * 16 * KST + dn8 * 8) * 2);
                ldsm_x2_trans(vl0, vl1, vlo_base + (kc * 16 * KST + dn8 * 8) * 2);
                mma16816(O[dn8], phi[kc], vh0, vh1);
                mma16816(O[dn8], plo[kc], vh0, vh1);
                mma16816(O[dn8], phi[kc], vl0, vl1);
            }
        }

        if (++cur == NBUF) cur = 0;
    }

    // ---------------- epilogue: Z reduce, O reduce, write out ----------------
    Zp0 += __shfl_xor_sync(0xffffffffu, Zp0, 1);
    Zp0 += __shfl_xor_sync(0xffffffffu, Zp0, 2);
    Zp1 += __shfl_xor_sync(0xffffffffu, Zp1, 1);
    Zp1 += __shfl_xor_sync(0xffffffffu, Zp1, 2);
    __syncthreads();              // all tiles done using smem
    if ((lane & 3) == 0) {
        Zbuf[wc * TM + wr * 16 + g]     = Zp0;
        Zbuf[wc * TM + wr * 16 + g + 8] = Zp1;
    }
    __syncthreads();
    if (tid < TM) {
        float iz = 1.0f / (Zbuf[tid] + Zbuf[TM + tid]);
        invZs[tid] = iz;
        g_zinv[(size_t)bh * SS + q0 + tid] = iz;
    }

    float* Obuf = (float*)dsm;    // [64][68] f32 = 17408 B
    const int r0 = wr * 16 + g, r1 = r0 + 8;
    if (wc == 0) {
        #pragma unroll
        for (int dn8 = 0; dn8 < 8; ++dn8) {
            *(float2*)(Obuf + r0 * 68 + dn8 * 8 + j2) = make_float2(O[dn8][0], O[dn8][1]);
            *(float2*)(Obuf + r1 * 68 + dn8 * 8 + j2) = make_float2(O[dn8][2], O[dn8][3]);
        }
    }
    __syncthreads();
    if (wc == 1) {
        #pragma unroll
        for (int dn8 = 0; dn8 < 8; ++dn8) {
            float2* p0 = (float2*)(Obuf + r0 * 68 + dn8 * 8 + j2);
            float2* p1 = (float2*)(Obuf + r1 * 68 + dn8 * 8 + j2);
            float2 a0 = *p0, a1 = *p1;
            a0.x += O[dn8][0]; a0.y += O[dn8][1];
            a1.x += O[dn8][2]; a1.y += O[dn8][3];
            *p0 = a0; *p1 = a1;
        }
    }
    __syncthreads();
    {
        int row = tid >> 2;
        int dq  = (tid & 3) * 16;
        float iz = invZs[row];
        float* orow = out + ((size_t)bh * SS + q0 + row) * DD + dq;
        #pragma unroll
        for (int i = 0; i < 4; ++i) {
            float4 x = *(float4*)(Obuf + row * 68 + dq + i * 4);
            x.x *= iz; x.y *= iz; x.z *= iz; x.w *= iz;
            *(float4*)(orow + i * 4) = x;
        }
    }
}

// kernel 3: attn[row][*] *= zinv[row]
__global__ __launch_bounds__(256)
void attn_norm_kernel(float* __restrict__ attn)
{
    size_t i = (size_t)blockIdx.x * blockDim.x + threadIdx.x;   // float4 index
    float4* a4 = (float4*)attn;
    float iz = __ldg(&g_zinv[i >> 9]);      // 512 float4 per row
    float4 x = a4[i];
    x.x *= iz; x.y *= iz; x.z *= iz; x.w *= iz;
    a4[i] = x;
}

extern "C" void kernel_launch(void* const* d_in, const int* in_sizes, int n_in,
                              void* d_out, int out_size)
{
    const float* q    = (const float*)d_in[0];
    const float* k    = (const float*)d_in[1];
    const float* v    = (const float*)d_in[2];
    const int*   mask = (const int*)d_in[3];

    float* out  = (float*)d_out;
    float* attn = out + (size_t)BB * HH * SS * DD;

    static bool configured = false;
    if (!configured) {
        cudaFuncSetAttribute(psdpa_mma_kernel,
                             cudaFuncAttributeMaxDynamicSharedMemorySize, SMEM_TOTAL);
        configured = true;
    }

    prepack_kernel<<<NELEM / 4 / 256, 256>>>(k, v);

    dim3 grid1(SS / TM, BB * HH);
    psdpa_mma_kernel<<<grid1, NTHREADS, SMEM_TOTAL>>>(q, mask, out, attn);

    size_t n4 = (size_t)BB * HH * SS * SS / 4;
    attn_norm_kernel<<<(unsigned)(n4 / 256), 256>>>(attn);
}

// round 8
// speedup vs baseline: 1.6500x; 1.0564x over previous
#include <cuda_runtime.h>
#include <cuda_bf16.h>
#include <cstdint>

#define BB 4
#define HH 16
#define SS 2048
#define DD 64

#define TM 64          // q rows per CTA
#define KT 64          // keys per tile
#define NTILES (SS / KT)
#define NTHREADS 256
#define KST 72         // smem row stride in halves (144B): conflict-free frag loads

#define TILE_B  (KT * KST * 2)     // 9216 bytes per part
#define BUF_B   (4 * TILE_B)       // Khi,Klo,Vhi,Vlo = 36864
#define NBUF 3
#define ZBUF_OFF (NBUF * BUF_B)    // 110592
#define INVZ_OFF (ZBUF_OFF + 512)
#define SMEM_TOTAL (INVZ_OFF + 256)

#define NELEM (BB * HH * SS * DD)  // 8388608
#define MWORDS (BB * SS * (SS / 32))  // 524288 uint32

__device__ float g_zinv[BB * HH * SS];
__device__ uint16_t g_khi[NELEM];
__device__ uint16_t g_klo[NELEM];
__device__ uint16_t g_vhi[NELEM];
__device__ uint16_t g_vlo[NELEM];
__device__ uint32_t g_mbits[MWORDS];

// ---------------- fast 2^y (FFMA only, deg-4), rel err ~3e-5 ----------------
__device__ __forceinline__ float fexp2f(float y) {
    float t = y + 12582912.0f;               // round-to-int via 1.5*2^23
    int   i = __float_as_int(t) << 23;
    float f = y - (t - 12582912.0f);
    float r = 9.6715857e-3f;
    r = fmaf(r, f, 5.5503714e-2f);
    r = fmaf(r, f, 2.4015310e-1f);
    r = fmaf(r, f, 6.9315315e-1f);
    r = fmaf(r, f, 1.0f);
    return __int_as_float(__float_as_int(r) + i);
}
#define L2E  1.4426950408889634f
#define SHL2 11.541560327111707f   // 8*log2(e):  exp(s-8) = 2^(s*L2E - SHL2)

// ---------------- wrappers ----------------
__device__ __forceinline__ void mma16816(float* c, const uint32_t* a, uint32_t b0, uint32_t b1) {
    asm volatile(
        "mma.sync.aligned.m16n8k16.row.col.f32.bf16.bf16.f32 "
        "{%0,%1,%2,%3},{%4,%5,%6,%7},{%8,%9},{%0,%1,%2,%3};"
        : "+f"(c[0]), "+f"(c[1]), "+f"(c[2]), "+f"(c[3])
        : "r"(a[0]), "r"(a[1]), "r"(a[2]), "r"(a[3]), "r"(b0), "r"(b1));
}
__device__ __forceinline__ void ldsm_x2_trans(uint32_t& r0, uint32_t& r1, uint32_t addr) {
    asm volatile("ldmatrix.sync.aligned.m8n8.x2.trans.shared.b16 {%0,%1}, [%2];"
                 : "=r"(r0), "=r"(r1) : "r"(addr));
}
__device__ __forceinline__ void ldsm_x4(uint32_t& r0, uint32_t& r1, uint32_t& r2, uint32_t& r3,
                                        uint32_t addr) {
    asm volatile("ldmatrix.sync.aligned.m8n8.x4.shared.b16 {%0,%1,%2,%3}, [%4];"
                 : "=r"(r0), "=r"(r1), "=r"(r2), "=r"(r3) : "r"(addr));
}
__device__ __forceinline__ uint32_t pack_bf16(float x, float y) {
    __nv_bfloat162 h = __floats2bfloat162_rn(x, y);
    return *(uint32_t*)&h;
}
__device__ __forceinline__ float bf_hi(uint32_t p) { return __bfloat162float(((__nv_bfloat162*)&p)->x); }
__device__ __forceinline__ float bf_lo(uint32_t p) { return __bfloat162float(((__nv_bfloat162*)&p)->y); }

__device__ __forceinline__ void cp16(uint32_t dst, const void* src) {
    asm volatile("cp.async.cg.shared.global [%0], [%1], 16;" :: "r"(dst), "l"(src));
}
#define CP_COMMIT() asm volatile("cp.async.commit_group;" ::: "memory")
#define CP_WAIT(n)  asm volatile("cp.async.wait_group %0;" :: "n"(n) : "memory")

// stage one tile (4 parts) via cp.async: 8 x 16B per thread
__device__ __forceinline__ void stage_async(uint32_t sbuf, size_t base, int tid) {
    const uint16_t* srcs[4] = {g_khi + base, g_klo + base, g_vhi + base, g_vlo + base};
    #pragma unroll
    for (int part = 0; part < 4; ++part) {
        uint32_t dpart = sbuf + part * TILE_B;
        #pragma unroll
        for (int it = 0; it < 2; ++it) {
            int idx = tid + it * NTHREADS;     // 0..511
            int row = idx >> 3;
            int seg = idx & 7;
            cp16(dpart + row * 144 + seg * 16, srcs[part] + row * 64 + seg * 8);
        }
    }
}

// ---------------- prepack: f32 K,V -> bf16 hi/lo ----------------
__global__ __launch_bounds__(256)
void prepack_kernel(const float* __restrict__ k, const float* __restrict__ v)
{
    size_t i = (size_t)blockIdx.x * 256 + threadIdx.x;   // float4 index
    float4 x = ((const float4*)k)[i];
    uint32_t h01 = pack_bf16(x.x, x.y);
    uint32_t h23 = pack_bf16(x.z, x.w);
    uint32_t l01 = pack_bf16(x.x - bf_hi(h01), x.y - bf_lo(h01));
    uint32_t l23 = pack_bf16(x.z - bf_hi(h23), x.w - bf_lo(h23));
    ((uint2*)g_khi)[i] = make_uint2(h01, h23);
    ((uint2*)g_klo)[i] = make_uint2(l01, l23);
    float4 y = ((const float4*)v)[i];
    h01 = pack_bf16(y.x, y.y);
    h23 = pack_bf16(y.z, y.w);
    l01 = pack_bf16(y.x - bf_hi(h01), y.y - bf_lo(h01));
    l23 = pack_bf16(y.z - bf_hi(h23), y.w - bf_lo(h23));
    ((uint2*)g_vhi)[i] = make_uint2(h01, h23);
    ((uint2*)g_vlo)[i] = make_uint2(l01, l23);
}

// ---------------- maskpack: int32 mask -> bitmask ----------------
__global__ __launch_bounds__(256)
void maskpack_kernel(const int* __restrict__ mask)
{
    size_t i = (size_t)blockIdx.x * 256 + threadIdx.x;
    int m = mask[i];
    uint32_t bits = __ballot_sync(0xffffffffu, m != 0);
    if ((threadIdx.x & 31) == 0) g_mbits[i >> 5] = bits;
}

__global__ __launch_bounds__(NTHREADS, 2)
void psdpa_mma_kernel(const float* __restrict__ q,
                      float* __restrict__ out,
                      float* __restrict__ attn)
{
    extern __shared__ __align__(16) char dsm[];
    float* Zbuf  = (float*)(dsm + ZBUF_OFF);
    float* invZs = (float*)(dsm + INVZ_OFF);
    const uint32_t sbase = (uint32_t)__cvta_generic_to_shared(dsm);

    const int tid  = threadIdx.x;
    const int w    = tid >> 5;
    const int lane = tid & 31;
    const int wr   = w & 3;        // row group (16 rows each)
    const int wc   = w >> 2;       // key-column half (32 keys each)
    const int g    = lane >> 2;
    const int j2   = (lane & 3) << 1;

    const int bh = blockIdx.y;
    const int b  = bh >> 4;
    const int q0 = blockIdx.x * TM;

    const float* qbase = q + ((size_t)bh * SS + q0) * DD;
    const size_t kvbase = (size_t)bh * SS * DD;

    // ---- Q fragments (scaled 1/8), hi/lo split; f32 staging in buffer region ----
    uint32_t qhi[4][4], qlo[4][4];
    {
        float* Qtmp = (float*)dsm;   // 16 KB
        const float4* qg = (const float4*)qbase;
        #pragma unroll
        for (int it = 0; it < 4; ++it) {
            int idx = tid + it * NTHREADS;
            int row = idx >> 4;
            int d4  = (idx & 15) << 2;
            float4 x = qg[idx];
            x.x *= 0.125f; x.y *= 0.125f; x.z *= 0.125f; x.w *= 0.125f;
            *(float4*)(Qtmp + row * DD + d4) = x;
        }
        __syncthreads();
        const int r0 = wr * 16 + g, r1 = r0 + 8;
        #pragma unroll
        for (int ks = 0; ks < 4; ++ks) {
            int d0 = ks * 16 + j2, d1 = d0 + 8;
            float2 x0 = *(float2*)(Qtmp + r0 * DD + d0);
            float2 x1 = *(float2*)(Qtmp + r1 * DD + d0);
            float2 x2 = *(float2*)(Qtmp + r0 * DD + d1);
            float2 x3 = *(float2*)(Qtmp + r1 * DD + d1);
            qhi[ks][0] = pack_bf16(x0.x, x0.y);
            qhi[ks][1] = pack_bf16(x1.x, x1.y);
            qhi[ks][2] = pack_bf16(x2.x, x2.y);
            qhi[ks][3] = pack_bf16(x3.x, x3.y);
            qlo[ks][0] = pack_bf16(x0.x - bf_hi(qhi[ks][0]), x0.y - bf_lo(qhi[ks][0]));
            qlo[ks][1] = pack_bf16(x1.x - bf_hi(qhi[ks][1]), x1.y - bf_lo(qhi[ks][1]));
            qlo[ks][2] = pack_bf16(x2.x - bf_hi(qhi[ks][2]), x2.y - bf_lo(qhi[ks][2]));
            qlo[ks][3] = pack_bf16(x3.x - bf_hi(qhi[ks][3]), x3.y - bf_lo(qhi[ks][3]));
        }
        __syncthreads();   // Qtmp region free before cp.async writes
    }

    const int qrow0 = q0 + wr * 16 + g;
    const int qrow8 = qrow0 + 8;
    const uint32_t* mb0 = g_mbits + ((size_t)b * SS + qrow0) * (SS / 32);
    const uint32_t* mb8 = g_mbits + ((size_t)b * SS + qrow8) * (SS / 32);
    float* arow0 = attn + ((size_t)bh * SS + qrow0) * SS;
    float* arow8 = attn + ((size_t)bh * SS + qrow8) * SS;

    // V frag (ldmatrix trans) per-lane offset within a part
    const int lkey = lane & 15;
    const uint32_t vfrag_off = ((wc * 32 + lkey) * KST) * 2;
    // K frag (ldmatrix non-trans) per-lane offset within a part:
    // lane i -> key = wc*32 + (i>>4)*8 + (i&7), d-half = ((i>>3)&1)*8
    const uint32_t kfrag_off =
        (((wc * 32 + (lane >> 4) * 8 + (lane & 7)) * KST) + ((lane >> 3) & 1) * 8) * 2;

    // ---- prologue: issue tiles 0 and 1 ----
    stage_async(sbase + 0 * BUF_B, kvbase + 0 * (size_t)KT * DD, tid);
    CP_COMMIT();
    stage_async(sbase + 1 * BUF_B, kvbase + 1 * (size_t)KT * DD, tid);
    CP_COMMIT();

    float O[8][4];
    #pragma unroll
    for (int i = 0; i < 8; ++i)
        #pragma unroll
        for (int c = 0; c < 4; ++c) O[i][c] = 0.0f;
    float Zp0 = 0.0f, Zp1 = 0.0f;

    int cur = 0;
    for (int t = 0; t < NTILES; ++t) {
        // prefetch this tile's mask bits (1 word covers this warp's 32 keys)
        uint32_t mw0 = mb0[2 * t + wc];
        uint32_t mw8 = mb8[2 * t + wc];

        if (t + 1 < NTILES) { CP_WAIT(1); } else { CP_WAIT(0); }
        __syncthreads();
        if (t + 2 < NTILES) {
            int nb = cur + 2; if (nb >= NBUF) nb -= NBUF;
            stage_async(sbase + nb * BUF_B, kvbase + (size_t)(t + 2) * KT * DD, tid);
            CP_COMMIT();
        }

        const uint32_t khi_b = sbase + cur * BUF_B + kfrag_off;
        const uint32_t klo_b = khi_b + TILE_B;
        const uint32_t vhi_base = sbase + cur * BUF_B + 2 * TILE_B + vfrag_off;
        const uint32_t vlo_base = vhi_base + TILE_B;

        // ---------------- QK^T : S[4 n8][4] over 32 keys ----------------
        float S[4][4];
        #pragma unroll
        for (int i = 0; i < 4; ++i)
            #pragma unroll
            for (int c = 0; c < 4; ++c) S[i][c] = 0.0f;

        #pragma unroll
        for (int ks = 0; ks < 4; ++ks) {
            uint32_t bh0[4], bh1[4], bl0[4], bl1[4];
            ldsm_x4(bh0[0], bh1[0], bh0[1], bh1[1], khi_b + ks * 32);
            ldsm_x4(bh0[2], bh1[2], bh0[3], bh1[3], khi_b + ks * 32 + 16 * KST * 2);
            ldsm_x4(bl0[0], bl1[0], bl0[1], bl1[1], klo_b + ks * 32);
            ldsm_x4(bl0[2], bl1[2], bl0[3], bl1[3], klo_b + ks * 32 + 16 * KST * 2);
            #pragma unroll
            for (int n8 = 0; n8 < 4; ++n8) mma16816(S[n8], qhi[ks], bh0[n8], bh1[n8]);
            #pragma unroll
            for (int n8 = 0; n8 < 4; ++n8) mma16816(S[n8], qlo[ks], bh0[n8], bh1[n8]);
            #pragma unroll
            for (int n8 = 0; n8 < 4; ++n8) mma16816(S[n8], qhi[ks], bl0[n8], bl1[n8]);
        }

        // ---------------- mask + exp + attn store + Z + P frags ----------------
        uint32_t phi[2][4], plo[2][4];
        #pragma unroll
        for (int gi = 0; gi < 4; ++gi) {
            int cb = t * KT + wc * 32 + gi * 8 + j2;
            int bit = gi * 8 + j2;
            float e0 = ((mw0 >> bit) & 1)       ? fexp2f(fmaf(S[gi][0], L2E, -SHL2)) : 0.0f;
            float e1 = ((mw0 >> (bit + 1)) & 1) ? fexp2f(fmaf(S[gi][1], L2E, -SHL2)) : 0.0f;
            float e2 = ((mw8 >> bit) & 1)       ? fexp2f(fmaf(S[gi][2], L2E, -SHL2)) : 0.0f;
            float e3 = ((mw8 >> (bit + 1)) & 1) ? fexp2f(fmaf(S[gi][3], L2E, -SHL2)) : 0.0f;
            *(float2*)(arow0 + cb) = make_float2(e0, e1);
            *(float2*)(arow8 + cb) = make_float2(e2, e3);
            Zp0 += e0 + e1;
            Zp1 += e2 + e3;
            int kc = gi >> 1, hh = (gi & 1) << 1;
            uint32_t h01 = pack_bf16(e0, e1);
            uint32_t h23 = pack_bf16(e2, e3);
            phi[kc][hh + 0] = h01;
            phi[kc][hh + 1] = h23;
            plo[kc][hh + 0] = pack_bf16(e0 - bf_hi(h01), e1 - bf_lo(h01));
            plo[kc][hh + 1] = pack_bf16(e2 - bf_hi(h23), e3 - bf_lo(h23));
        }

        // ---------------- P @ V : O[8 dn8][4] ----------------
        #pragma unroll
        for (int kc = 0; kc < 2; ++kc) {
            #pragma unroll
            for (int dn8 = 0; dn8 < 8; ++dn8) {
                uint32_t vh0, vh1, vl0, vl1;
                ldsm_x2_trans(vh0, vh1, vhi_base + (kc * 16 * KST + dn8 * 8) * 2);
                ldsm_x2_trans(vl0, vl1, vlo_base + (kc * 16 * KST + dn8 * 8) * 2);
                mma16816(O[dn8], phi[kc], vh0, vh1);
                mma16816(O[dn8], plo[kc], vh0, vh1);
                mma16816(O[dn8], phi[kc], vl0, vl1);
            }
        }

        if (++cur == NBUF) cur = 0;
    }

    // ---------------- epilogue: Z reduce, O reduce, write out ----------------
    Zp0 += __shfl_xor_sync(0xffffffffu, Zp0, 1);
    Zp0 += __shfl_xor_sync(0xffffffffu, Zp0, 2);
    Zp1 += __shfl_xor_sync(0xffffffffu, Zp1, 1);
    Zp1 += __shfl_xor_sync(0xffffffffu, Zp1, 2);
    __syncthreads();              // all tiles done using smem
    if ((lane & 3) == 0) {
        Zbuf[wc * TM + wr * 16 + g]     = Zp0;
        Zbuf[wc * TM + wr * 16 + g + 8] = Zp1;
    }
    __syncthreads();
    if (tid < TM) {
        float iz = 1.0f / (Zbuf[tid] + Zbuf[TM + tid]);
        invZs[tid] = iz;
        g_zinv[(size_t)bh * SS + q0 + tid] = iz;
    }

    float* Obuf = (float*)dsm;    // [64][68] f32 = 17408 B
    const int r0 = wr * 16 + g, r1 = r0 + 8;
    if (wc == 0) {
        #pragma unroll
        for (int dn8 = 0; dn8 < 8; ++dn8) {
            *(float2*)(Obuf + r0 * 68 + dn8 * 8 + j2) = make_float2(O[dn8][0], O[dn8][1]);
            *(float2*)(Obuf + r1 * 68 + dn8 * 8 + j2) = make_float2(O[dn8][2], O[dn8][3]);
        }
    }
    __syncthreads();
    if (wc == 1) {
        #pragma unroll
        for (int dn8 = 0; dn8 < 8; ++dn8) {
            float2* p0 = (float2*)(Obuf + r0 * 68 + dn8 * 8 + j2);
            float2* p1 = (float2*)(Obuf + r1 * 68 + dn8 * 8 + j2);
            float2 a0 = *p0, a1 = *p1;
            a0.x += O[dn8][0]; a0.y += O[dn8][1];
            a1.x += O[dn8][2]; a1.y += O[dn8][3];
            *p0 = a0; *p1 = a1;
        }
    }
    __syncthreads();
    {
        int row = tid >> 2;
        int dq  = (tid & 3) * 16;
        float iz = invZs[row];
        float* orow = out + ((size_t)bh * SS + q0 + row) * DD + dq;
        #pragma unroll
        for (int i = 0; i < 4; ++i) {
            float4 x = *(float4*)(Obuf + row * 68 + dq + i * 4);
            x.x *= iz; x.y *= iz; x.z *= iz; x.w *= iz;
            *(float4*)(orow + i * 4) = x;
        }
    }
}

// kernel 4: attn[row][*] *= zinv[row]
__global__ __launch_bounds__(256)
void attn_norm_kernel(float* __restrict__ attn)
{
    size_t i = (size_t)blockIdx.x * blockDim.x + threadIdx.x;   // float4 index
    float4* a4 = (float4*)attn;
    float iz = __ldg(&g_zinv[i >> 9]);      // 512 float4 per row
    float4 x = a4[i];
    x.x *= iz; x.y *= iz; x.z *= iz; x.w *= iz;
    a4[i] = x;
}

extern "C" void kernel_launch(void* const* d_in, const int* in_sizes, int n_in,
                              void* d_out, int out_size)
{
    const float* q    = (const float*)d_in[0];
    const float* k    = (const float*)d_in[1];
    const float* v    = (const float*)d_in[2];
    const int*   mask = (const int*)d_in[3];

    float* out  = (float*)d_out;
    float* attn = out + (size_t)BB * HH * SS * DD;

    static bool configured = false;
    if (!configured) {
        cudaFuncSetAttribute(psdpa_mma_kernel,
                             cudaFuncAttributeMaxDynamicSharedMemorySize, SMEM_TOTAL);
        configured = true;
    }

    prepack_kernel<<<NELEM / 4 / 256, 256>>>(k, v);
    maskpack_kernel<<<(BB * SS * SS) / 256, 256>>>(mask);

    dim3 grid1(SS / TM, BB * HH);
    psdpa_mma_kernel<<<grid1, NTHREADS, SMEM_TOTAL>>>(q, out, attn);

    size_t n4 = (size_t)BB * HH * SS * SS / 4;
    attn_norm_kernel<<<(unsigned)(n4 / 256), 256>>>(attn);
}

// round 9
// speedup vs baseline: 1.8762x; 1.1370x over previous
#include <cuda_runtime.h>
#include <cuda_bf16.h>
#include <cstdint>

#define BB 4
#define HH 16
#define SS 2048
#define DD 64

#define TM 64          // q rows per CTA
#define KT 64          // keys per tile
#define NTILES (SS / KT)
#define NTHREADS 256
#define KST 72         // smem row stride in halves (144B): conflict-free frag loads

#define TILE_B  (KT * KST * 2)     // 9216 bytes per part
#define BUF_B   (4 * TILE_B)       // Khi,Klo,Vhi,Vlo = 36864
#define NBUF 3
#define ZBUF_OFF (NBUF * BUF_B)    // 110592
#define INVZ_OFF (ZBUF_OFF + 512)
#define SMEM_TOTAL (INVZ_OFF + 256)

#define NELEM (BB * HH * SS * DD)  // 8388608
#define MWORDS (BB * SS * (SS / 32))  // 524288 uint32

__device__ uint16_t g_khi[NELEM];
__device__ uint16_t g_klo[NELEM];
__device__ uint16_t g_vhi[NELEM];
__device__ uint16_t g_vlo[NELEM];
__device__ uint32_t g_mbits[MWORDS];

// ---------------- fast 2^y (FFMA only, deg-4), rel err ~3e-5 ----------------
__device__ __forceinline__ float fexp2f(float y) {
    float t = y + 12582912.0f;               // round-to-int via 1.5*2^23
    int   i = __float_as_int(t) << 23;
    float f = y - (t - 12582912.0f);
    float r = 9.6715857e-3f;
    r = fmaf(r, f, 5.5503714e-2f);
    r = fmaf(r, f, 2.4015310e-1f);
    r = fmaf(r, f, 6.9315315e-1f);
    r = fmaf(r, f, 1.0f);
    return __int_as_float(__float_as_int(r) + i);
}
#define L2E  1.4426950408889634f
#define SHL2 11.541560327111707f   // 8*log2(e):  exp(s-8) = 2^(s*L2E - SHL2)

// ---------------- wrappers ----------------
__device__ __forceinline__ void mma16816(float* c, const uint32_t* a, uint32_t b0, uint32_t b1) {
    asm volatile(
        "mma.sync.aligned.m16n8k16.row.col.f32.bf16.bf16.f32 "
        "{%0,%1,%2,%3},{%4,%5,%6,%7},{%8,%9},{%0,%1,%2,%3};"
        : "+f"(c[0]), "+f"(c[1]), "+f"(c[2]), "+f"(c[3])
        : "r"(a[0]), "r"(a[1]), "r"(a[2]), "r"(a[3]), "r"(b0), "r"(b1));
}
__device__ __forceinline__ void ldsm_x2_trans(uint32_t& r0, uint32_t& r1, uint32_t addr) {
    asm volatile("ldmatrix.sync.aligned.m8n8.x2.trans.shared.b16 {%0,%1}, [%2];"
                 : "=r"(r0), "=r"(r1) : "r"(addr));
}
__device__ __forceinline__ void ldsm_x4(uint32_t& r0, uint32_t& r1, uint32_t& r2, uint32_t& r3,
                                        uint32_t addr) {
    asm volatile("ldmatrix.sync.aligned.m8n8.x4.shared.b16 {%0,%1,%2,%3}, [%4];"
                 : "=r"(r0), "=r"(r1), "=r"(r2), "=r"(r3) : "r"(addr));
}
__device__ __forceinline__ uint32_t pack_bf16(float x, float y) {
    __nv_bfloat162 h = __floats2bfloat162_rn(x, y);
    return *(uint32_t*)&h;
}
__device__ __forceinline__ float bf_hi(uint32_t p) { return __bfloat162float(((__nv_bfloat162*)&p)->x); }
__device__ __forceinline__ float bf_lo(uint32_t p) { return __bfloat162float(((__nv_bfloat162*)&p)->y); }

__device__ __forceinline__ void cp16(uint32_t dst, const void* src) {
    asm volatile("cp.async.cg.shared.global [%0], [%1], 16;" :: "r"(dst), "l"(src));
}
#define CP_COMMIT() asm volatile("cp.async.commit_group;" ::: "memory")
#define CP_WAIT(n)  asm volatile("cp.async.wait_group %0;" :: "n"(n) : "memory")

// stage one tile (4 parts) via cp.async: 8 x 16B per thread
__device__ __forceinline__ void stage_async(uint32_t sbuf, size_t base, int tid) {
    const uint16_t* srcs[4] = {g_khi + base, g_klo + base, g_vhi + base, g_vlo + base};
    #pragma unroll
    for (int part = 0; part < 4; ++part) {
        uint32_t dpart = sbuf + part * TILE_B;
        #pragma unroll
        for (int it = 0; it < 2; ++it) {
            int idx = tid + it * NTHREADS;     // 0..511
            int row = idx >> 3;
            int seg = idx & 7;
            cp16(dpart + row * 144 + seg * 16, srcs[part] + row * 64 + seg * 8);
        }
    }
}

// ---------------- prepack: f32 K,V -> bf16 hi/lo ----------------
__global__ __launch_bounds__(256)
void prepack_kernel(const float* __restrict__ k, const float* __restrict__ v)
{
    size_t i = (size_t)blockIdx.x * 256 + threadIdx.x;   // float4 index
    float4 x = ((const float4*)k)[i];
    uint32_t h01 = pack_bf16(x.x, x.y);
    uint32_t h23 = pack_bf16(x.z, x.w);
    uint32_t l01 = pack_bf16(x.x - bf_hi(h01), x.y - bf_lo(h01));
    uint32_t l23 = pack_bf16(x.z - bf_hi(h23), x.w - bf_lo(h23));
    ((uint2*)g_khi)[i] = make_uint2(h01, h23);
    ((uint2*)g_klo)[i] = make_uint2(l01, l23);
    float4 y = ((const float4*)v)[i];
    h01 = pack_bf16(y.x, y.y);
    h23 = pack_bf16(y.z, y.w);
    l01 = pack_bf16(y.x - bf_hi(h01), y.y - bf_lo(h01));
    l23 = pack_bf16(y.z - bf_hi(h23), y.w - bf_lo(h23));
    ((uint2*)g_vhi)[i] = make_uint2(h01, h23);
    ((uint2*)g_vlo)[i] = make_uint2(l01, l23);
}

// ---------------- maskpack: int32 mask -> bitmask ----------------
__global__ __launch_bounds__(256)
void maskpack_kernel(const int* __restrict__ mask)
{
    size_t i = (size_t)blockIdx.x * 256 + threadIdx.x;
    int m = mask[i];
    uint32_t bits = __ballot_sync(0xffffffffu, m != 0);
    if ((threadIdx.x & 31) == 0) g_mbits[i >> 5] = bits;
}

__global__ __launch_bounds__(NTHREADS, 2)
void psdpa_mma_kernel(const float* __restrict__ q,
                      float* __restrict__ out,
                      float* __restrict__ attn)
{
    extern __shared__ __align__(16) char dsm[];
    float* Zbuf  = (float*)(dsm + ZBUF_OFF);
    float* invZs = (float*)(dsm + INVZ_OFF);
    const uint32_t sbase = (uint32_t)__cvta_generic_to_shared(dsm);

    const int tid  = threadIdx.x;
    const int w    = tid >> 5;
    const int lane = tid & 31;
    const int wr   = w & 3;        // row group (16 rows each)
    const int wc   = w >> 2;       // key-column half (32 keys each)
    const int g    = lane >> 2;
    const int j2   = (lane & 3) << 1;

    const int bh = blockIdx.y;
    const int b  = bh >> 4;
    const int q0 = blockIdx.x * TM;

    const float* qbase = q + ((size_t)bh * SS + q0) * DD;
    const size_t kvbase = (size_t)bh * SS * DD;

    // ---- Q fragments (scaled 1/8), hi/lo split; f32 staging in buffer region ----
    uint32_t qhi[4][4], qlo[4][4];
    {
        float* Qtmp = (float*)dsm;   // 16 KB
        const float4* qg = (const float4*)qbase;
        #pragma unroll
        for (int it = 0; it < 4; ++it) {
            int idx = tid + it * NTHREADS;
            int row = idx >> 4;
            int d4  = (idx & 15) << 2;
            float4 x = qg[idx];
            x.x *= 0.125f; x.y *= 0.125f; x.z *= 0.125f; x.w *= 0.125f;
            *(float4*)(Qtmp + row * DD + d4) = x;
        }
        __syncthreads();
        const int r0 = wr * 16 + g, r1 = r0 + 8;
        #pragma unroll
        for (int ks = 0; ks < 4; ++ks) {
            int d0 = ks * 16 + j2, d1 = d0 + 8;
            float2 x0 = *(float2*)(Qtmp + r0 * DD + d0);
            float2 x1 = *(float2*)(Qtmp + r1 * DD + d0);
            float2 x2 = *(float2*)(Qtmp + r0 * DD + d1);
            float2 x3 = *(float2*)(Qtmp + r1 * DD + d1);
            qhi[ks][0] = pack_bf16(x0.x, x0.y);
            qhi[ks][1] = pack_bf16(x1.x, x1.y);
            qhi[ks][2] = pack_bf16(x2.x, x2.y);
            qhi[ks][3] = pack_bf16(x3.x, x3.y);
            qlo[ks][0] = pack_bf16(x0.x - bf_hi(qhi[ks][0]), x0.y - bf_lo(qhi[ks][0]));
            qlo[ks][1] = pack_bf16(x1.x - bf_hi(qhi[ks][1]), x1.y - bf_lo(qhi[ks][1]));
            qlo[ks][2] = pack_bf16(x2.x - bf_hi(qhi[ks][2]), x2.y - bf_lo(qhi[ks][2]));
            qlo[ks][3] = pack_bf16(x3.x - bf_hi(qhi[ks][3]), x3.y - bf_lo(qhi[ks][3]));
        }
        __syncthreads();   // Qtmp region free before cp.async writes
    }

    const int qrow0 = q0 + wr * 16 + g;
    const int qrow8 = qrow0 + 8;
    const uint32_t* mb0 = g_mbits + ((size_t)b * SS + qrow0) * (SS / 32);
    const uint32_t* mb8 = g_mbits + ((size_t)b * SS + qrow8) * (SS / 32);
    float* arow0 = attn + ((size_t)bh * SS + qrow0) * SS;
    float* arow8 = attn + ((size_t)bh * SS + qrow8) * SS;

    // V frag (ldmatrix trans) per-lane offset within a part
    const int lkey = lane & 15;
    const uint32_t vfrag_off = ((wc * 32 + lkey) * KST) * 2;
    // K frag (ldmatrix non-trans) per-lane offset within a part
    const uint32_t kfrag_off =
        (((wc * 32 + (lane >> 4) * 8 + (lane & 7)) * KST) + ((lane >> 3) & 1) * 8) * 2;

    // ---- prologue: issue tiles 0 and 1 ----
    stage_async(sbase + 0 * BUF_B, kvbase + 0 * (size_t)KT * DD, tid);
    CP_COMMIT();
    stage_async(sbase + 1 * BUF_B, kvbase + 1 * (size_t)KT * DD, tid);
    CP_COMMIT();

    float O[8][4];
    #pragma unroll
    for (int i = 0; i < 8; ++i)
        #pragma unroll
        for (int c = 0; c < 4; ++c) O[i][c] = 0.0f;
    float Zp0 = 0.0f, Zp1 = 0.0f;

    int cur = 0;
    for (int t = 0; t < NTILES; ++t) {
        // prefetch this tile's mask bits (1 word covers this warp's 32 keys)
        uint32_t mw0 = mb0[2 * t + wc];
        uint32_t mw8 = mb8[2 * t + wc];

        if (t + 1 < NTILES) { CP_WAIT(1); } else { CP_WAIT(0); }
        __syncthreads();
        if (t + 2 < NTILES) {
            int nb = cur + 2; if (nb >= NBUF) nb -= NBUF;
            stage_async(sbase + nb * BUF_B, kvbase + (size_t)(t + 2) * KT * DD, tid);
            CP_COMMIT();
        }

        const uint32_t khi_b = sbase + cur * BUF_B + kfrag_off;
        const uint32_t klo_b = khi_b + TILE_B;
        const uint32_t vhi_base = sbase + cur * BUF_B + 2 * TILE_B + vfrag_off;
        const uint32_t vlo_base = vhi_base + TILE_B;

        // ---------------- QK^T : S[4 n8][4] over 32 keys ----------------
        float S[4][4];
        #pragma unroll
        for (int i = 0; i < 4; ++i)
            #pragma unroll
            for (int c = 0; c < 4; ++c) S[i][c] = 0.0f;

        #pragma unroll
        for (int ks = 0; ks < 4; ++ks) {
            uint32_t bh0[4], bh1[4], bl0[4], bl1[4];
            ldsm_x4(bh0[0], bh1[0], bh0[1], bh1[1], khi_b + ks * 32);
            ldsm_x4(bh0[2], bh1[2], bh0[3], bh1[3], khi_b + ks * 32 + 16 * KST * 2);
            ldsm_x4(bl0[0], bl1[0], bl0[1], bl1[1], klo_b + ks * 32);
            ldsm_x4(bl0[2], bl1[2], bl0[3], bl1[3], klo_b + ks * 32 + 16 * KST * 2);
            #pragma unroll
            for (int n8 = 0; n8 < 4; ++n8) mma16816(S[n8], qhi[ks], bh0[n8], bh1[n8]);
            #pragma unroll
            for (int n8 = 0; n8 < 4; ++n8) mma16816(S[n8], qlo[ks], bh0[n8], bh1[n8]);
            #pragma unroll
            for (int n8 = 0; n8 < 4; ++n8) mma16816(S[n8], qhi[ks], bl0[n8], bl1[n8]);
        }

        // ---------------- mask + exp + attn store + Z + P frags ----------------
        uint32_t phi[2][4], plo[2][4];
        #pragma unroll
        for (int gi = 0; gi < 4; ++gi) {
            int cb = t * KT + wc * 32 + gi * 8 + j2;
            int bit = gi * 8 + j2;
            float e0 = ((mw0 >> bit) & 1)       ? fexp2f(fmaf(S[gi][0], L2E, -SHL2)) : 0.0f;
            float e1 = ((mw0 >> (bit + 1)) & 1) ? fexp2f(fmaf(S[gi][1], L2E, -SHL2)) : 0.0f;
            float e2 = ((mw8 >> bit) & 1)       ? fexp2f(fmaf(S[gi][2], L2E, -SHL2)) : 0.0f;
            float e3 = ((mw8 >> (bit + 1)) & 1) ? fexp2f(fmaf(S[gi][3], L2E, -SHL2)) : 0.0f;
            *(float2*)(arow0 + cb) = make_float2(e0, e1);
            *(float2*)(arow8 + cb) = make_float2(e2, e3);
            Zp0 += e0 + e1;
            Zp1 += e2 + e3;
            int kc = gi >> 1, hh = (gi & 1) << 1;
            uint32_t h01 = pack_bf16(e0, e1);
            uint32_t h23 = pack_bf16(e2, e3);
            phi[kc][hh + 0] = h01;
            phi[kc][hh + 1] = h23;
            plo[kc][hh + 0] = pack_bf16(e0 - bf_hi(h01), e1 - bf_lo(h01));
            plo[kc][hh + 1] = pack_bf16(e2 - bf_hi(h23), e3 - bf_lo(h23));
        }

        // ---------------- P @ V : O[8 dn8][4] ----------------
        #pragma unroll
        for (int kc = 0; kc < 2; ++kc) {
            #pragma unroll
            for (int dn8 = 0; dn8 < 8; ++dn8) {
                uint32_t vh0, vh1, vl0, vl1;
                ldsm_x2_trans(vh0, vh1, vhi_base + (kc * 16 * KST + dn8 * 8) * 2);
                ldsm_x2_trans(vl0, vl1, vlo_base + (kc * 16 * KST + dn8 * 8) * 2);
                mma16816(O[dn8], phi[kc], vh0, vh1);
                mma16816(O[dn8], plo[kc], vh0, vh1);
                mma16816(O[dn8], phi[kc], vl0, vl1);
            }
        }

        if (++cur == NBUF) cur = 0;
    }

    // ---------------- epilogue: Z reduce ----------------
    Zp0 += __shfl_xor_sync(0xffffffffu, Zp0, 1);
    Zp0 += __shfl_xor_sync(0xffffffffu, Zp0, 2);
    Zp1 += __shfl_xor_sync(0xffffffffu, Zp1, 1);
    Zp1 += __shfl_xor_sync(0xffffffffu, Zp1, 2);
    __syncthreads();              // all tiles done using smem; attn writes visible
    if ((lane & 3) == 0) {
        Zbuf[wc * TM + wr * 16 + g]     = Zp0;
        Zbuf[wc * TM + wr * 16 + g + 8] = Zp1;
    }
    __syncthreads();
    if (tid < TM) {
        invZs[tid] = 1.0f / (Zbuf[tid] + Zbuf[TM + tid]);
    }

    // ---------------- O reduce + write out ----------------
    float* Obuf = (float*)dsm;    // [64][68] f32 = 17408 B
    const int r0 = wr * 16 + g, r1 = r0 + 8;
    if (wc == 0) {
        #pragma unroll
        for (int dn8 = 0; dn8 < 8; ++dn8) {
            *(float2*)(Obuf + r0 * 68 + dn8 * 8 + j2) = make_float2(O[dn8][0], O[dn8][1]);
            *(float2*)(Obuf + r1 * 68 + dn8 * 8 + j2) = make_float2(O[dn8][2], O[dn8][3]);
        }
    }
    __syncthreads();
    if (wc == 1) {
        #pragma unroll
        for (int dn8 = 0; dn8 < 8; ++dn8) {
            float2* p0 = (float2*)(Obuf + r0 * 68 + dn8 * 8 + j2);
            float2* p1 = (float2*)(Obuf + r1 * 68 + dn8 * 8 + j2);
            float2 a0 = *p0, a1 = *p1;
            a0.x += O[dn8][0]; a0.y += O[dn8][1];
            a1.x += O[dn8][2]; a1.y += O[dn8][3];
            *p0 = a0; *p1 = a1;
        }
    }
    __syncthreads();
    {
        int row = tid >> 2;
        int dq  = (tid & 3) * 16;
        float iz = invZs[row];
        float* orow = out + ((size_t)bh * SS + q0 + row) * DD + dq;
        #pragma unroll
        for (int i = 0; i < 4; ++i) {
            float4 x = *(float4*)(Obuf + row * 68 + dq + i * 4);
            x.x *= iz; x.y *= iz; x.z *= iz; x.w *= iz;
            *(float4*)(orow + i * 4) = x;
        }
    }

    // ---------------- fused attn normalization (replaces attn_norm kernel) ----
    // warp w normalizes rows {w, w+8, ..., w+56}; fully coalesced float4 walk.
    {
        float* attn_base = attn + ((size_t)bh * SS + q0) * SS;
        #pragma unroll
        for (int rr = 0; rr < 8; ++rr) {
            int row = w + 8 * rr;
            float iz = invZs[row];
            float4* a4 = (float4*)(attn_base + (size_t)row * SS);
            #pragma unroll 4
            for (int i = 0; i < 16; ++i) {
                int idx = lane + 32 * i;
                float4 x = a4[idx];
                x.x *= iz; x.y *= iz; x.z *= iz; x.w *= iz;
                a4[idx] = x;
            }
        }
    }
}

extern "C" void kernel_launch(void* const* d_in, const int* in_sizes, int n_in,
                              void* d_out, int out_size)
{
    const float* q    = (const float*)d_in[0];
    const float* k    = (const float*)d_in[1];
    const float* v    = (const float*)d_in[2];
    const int*   mask = (const int*)d_in[3];

    float* out  = (float*)d_out;
    float* attn = out + (size_t)BB * HH * SS * DD;

    static bool configured = false;
    if (!configured) {
        cudaFuncSetAttribute(psdpa_mma_kernel,
                             cudaFuncAttributeMaxDynamicSharedMemorySize, SMEM_TOTAL);
        configured = true;
    }

    prepack_kernel<<<NELEM / 4 / 256, 256>>>(k, v);
    maskpack_kernel<<<(BB * SS * SS) / 256, 256>>>(mask);

    dim3 grid1(SS / TM, BB * HH);
    psdpa_mma_kernel<<<grid1, NTHREADS, SMEM_TOTAL>>>(q, out, attn);
}

// round 10
// speedup vs baseline: 2.0814x; 1.1094x over previous
#include <cuda_runtime.h>
#include <cuda_bf16.h>
#include <cuda_fp16.h>
#include <cstdint>

#define BB 4
#define HH 16
#define SS 2048
#define DD 64

#define TM 64          // q rows per CTA
#define KT 64          // keys per tile
#define NTILES (SS / KT)
#define NTHREADS 256
#define KST 72         // smem row stride in halves (144B): conflict-free frag loads

#define TILE_B  (KT * KST * 2)     // 9216 bytes per part
#define NPART 3                    // Khi, Klo, Vh
#define BUF_B   (NPART * TILE_B)   // 27648
#define NBUF 3
#define ZBUF_OFF (NBUF * BUF_B)    // 82944
#define INVZ_OFF (ZBUF_OFF + 512)
#define SMEM_TOTAL (INVZ_OFF + 256)

#define NELEM (BB * HH * SS * DD)  // 8388608
#define MWORDS (BB * SS * (SS / 32))  // 524288 uint32

__device__ uint16_t g_khi[NELEM];
__device__ uint16_t g_klo[NELEM];
__device__ uint16_t g_vh[NELEM];
__device__ uint32_t g_mbits[MWORDS];

// ---------------- fast 2^y (FFMA only, deg-4), rel err ~3e-5 ----------------
__device__ __forceinline__ float fexp2f(float y) {
    float t = y + 12582912.0f;               // round-to-int via 1.5*2^23
    int   i = __float_as_int(t) << 23;
    float f = y - (t - 12582912.0f);
    float r = 9.6715857e-3f;
    r = fmaf(r, f, 5.5503714e-2f);
    r = fmaf(r, f, 2.4015310e-1f);
    r = fmaf(r, f, 6.9315315e-1f);
    r = fmaf(r, f, 1.0f);
    return __int_as_float(__float_as_int(r) + i);
}
#define L2E  1.4426950408889634f
#define SHL2 11.541560327111707f   // 8*log2(e):  exp(s-8) = 2^(s*L2E - SHL2)

// ---------------- wrappers ----------------
__device__ __forceinline__ void mma16816(float* c, const uint32_t* a, uint32_t b0, uint32_t b1) {
    asm volatile(
        "mma.sync.aligned.m16n8k16.row.col.f32.bf16.bf16.f32 "
        "{%0,%1,%2,%3},{%4,%5,%6,%7},{%8,%9},{%0,%1,%2,%3};"
        : "+f"(c[0]), "+f"(c[1]), "+f"(c[2]), "+f"(c[3])
        : "r"(a[0]), "r"(a[1]), "r"(a[2]), "r"(a[3]), "r"(b0), "r"(b1));
}
__device__ __forceinline__ void mma16816h(float* c, const uint32_t* a, uint32_t b0, uint32_t b1) {
    asm volatile(
        "mma.sync.aligned.m16n8k16.row.col.f32.f16.f16.f32 "
        "{%0,%1,%2,%3},{%4,%5,%6,%7},{%8,%9},{%0,%1,%2,%3};"
        : "+f"(c[0]), "+f"(c[1]), "+f"(c[2]), "+f"(c[3])
        : "r"(a[0]), "r"(a[1]), "r"(a[2]), "r"(a[3]), "r"(b0), "r"(b1));
}
__device__ __forceinline__ void ldsm_x2_trans(uint32_t& r0, uint32_t& r1, uint32_t addr) {
    asm volatile("ldmatrix.sync.aligned.m8n8.x2.trans.shared.b16 {%0,%1}, [%2];"
                 : "=r"(r0), "=r"(r1) : "r"(addr));
}
__device__ __forceinline__ void ldsm_x4(uint32_t& r0, uint32_t& r1, uint32_t& r2, uint32_t& r3,
                                        uint32_t addr) {
    asm volatile("ldmatrix.sync.aligned.m8n8.x4.shared.b16 {%0,%1,%2,%3}, [%4];"
                 : "=r"(r0), "=r"(r1), "=r"(r2), "=r"(r3) : "r"(addr));
}
__device__ __forceinline__ uint32_t pack_bf16(float x, float y) {
    __nv_bfloat162 h = __floats2bfloat162_rn(x, y);
    return *(uint32_t*)&h;
}
__device__ __forceinline__ uint32_t pack_f16(float x, float y) {
    __half2 h = __floats2half2_rn(x, y);
    return *(uint32_t*)&h;
}
__device__ __forceinline__ float bf_hi(uint32_t p) { return __bfloat162float(((__nv_bfloat162*)&p)->x); }
__device__ __forceinline__ float bf_lo(uint32_t p) { return __bfloat162float(((__nv_bfloat162*)&p)->y); }

__device__ __forceinline__ void cp16(uint32_t dst, const void* src) {
    asm volatile("cp.async.cg.shared.global [%0], [%1], 16;" :: "r"(dst), "l"(src));
}
#define CP_COMMIT() asm volatile("cp.async.commit_group;" ::: "memory")
#define CP_WAIT(n)  asm volatile("cp.async.wait_group %0;" :: "n"(n) : "memory")

// stage one tile (3 parts) via cp.async: 6 x 16B per thread
__device__ __forceinline__ void stage_async(uint32_t sbuf, size_t base, int tid) {
    const uint16_t* srcs[NPART] = {g_khi + base, g_klo + base, g_vh + base};
    #pragma unroll
    for (int part = 0; part < NPART; ++part) {
        uint32_t dpart = sbuf + part * TILE_B;
        #pragma unroll
        for (int it = 0; it < 2; ++it) {
            int idx = tid + it * NTHREADS;     // 0..511
            int row = idx >> 3;
            int seg = idx & 7;
            cp16(dpart + row * 144 + seg * 16, srcs[part] + row * 64 + seg * 8);
        }
    }
}

// ---------------- prepack: f32 K -> bf16 hi/lo, V -> fp16 ----------------
__global__ __launch_bounds__(256)
void prepack_kernel(const float* __restrict__ k, const float* __restrict__ v)
{
    size_t i = (size_t)blockIdx.x * 256 + threadIdx.x;   // float4 index
    float4 x = ((const float4*)k)[i];
    uint32_t h01 = pack_bf16(x.x, x.y);
    uint32_t h23 = pack_bf16(x.z, x.w);
    uint32_t l01 = pack_bf16(x.x - bf_hi(h01), x.y - bf_lo(h01));
    uint32_t l23 = pack_bf16(x.z - bf_hi(h23), x.w - bf_lo(h23));
    ((uint2*)g_khi)[i] = make_uint2(h01, h23);
    ((uint2*)g_klo)[i] = make_uint2(l01, l23);
    float4 y = ((const float4*)v)[i];
    ((uint2*)g_vh)[i] = make_uint2(pack_f16(y.x, y.y), pack_f16(y.z, y.w));
}

// ---------------- maskpack: int32 mask -> bitmask ----------------
__global__ __launch_bounds__(256)
void maskpack_kernel(const int* __restrict__ mask)
{
    size_t i = (size_t)blockIdx.x * 256 + threadIdx.x;
    int m = mask[i];
    uint32_t bits = __ballot_sync(0xffffffffu, m != 0);
    if ((threadIdx.x & 31) == 0) g_mbits[i >> 5] = bits;
}

__global__ __launch_bounds__(NTHREADS, 2)
void psdpa_mma_kernel(const float* __restrict__ q,
                      float* __restrict__ out,
                      float* __restrict__ attn)
{
    extern __shared__ __align__(16) char dsm[];
    float* Zbuf  = (float*)(dsm + ZBUF_OFF);
    float* invZs = (float*)(dsm + INVZ_OFF);
    const uint32_t sbase = (uint32_t)__cvta_generic_to_shared(dsm);

    const int tid  = threadIdx.x;
    const int w    = tid >> 5;
    const int lane = tid & 31;
    const int wr   = w & 3;        // row group (16 rows each)
    const int wc   = w >> 2;       // key-column half (32 keys each)
    const int g    = lane >> 2;
    const int j2   = (lane & 3) << 1;

    const int bh = blockIdx.y;
    const int b  = bh >> 4;
    const int q0 = blockIdx.x * TM;

    const float* qbase = q + ((size_t)bh * SS + q0) * DD;
    const size_t kvbase = (size_t)bh * SS * DD;

    // ---- Q fragments (scaled 1/8), hi/lo split; f32 staging in buffer region ----
    uint32_t qhi[4][4], qlo[4][4];
    {
        float* Qtmp = (float*)dsm;   // 16 KB
        const float4* qg = (const float4*)qbase;
        #pragma unroll
        for (int it = 0; it < 4; ++it) {
            int idx = tid + it * NTHREADS;
            int row = idx >> 4;
            int d4  = (idx & 15) << 2;
            float4 x = qg[idx];
            x.x *= 0.125f; x.y *= 0.125f; x.z *= 0.125f; x.w *= 0.125f;
            *(float4*)(Qtmp + row * DD + d4) = x;
        }
        __syncthreads();
        const int r0 = wr * 16 + g, r1 = r0 + 8;
        #pragma unroll
        for (int ks = 0; ks < 4; ++ks) {
            int d0 = ks * 16 + j2, d1 = d0 + 8;
            float2 x0 = *(float2*)(Qtmp + r0 * DD + d0);
            float2 x1 = *(float2*)(Qtmp + r1 * DD + d0);
            float2 x2 = *(float2*)(Qtmp + r0 * DD + d1);
            float2 x3 = *(float2*)(Qtmp + r1 * DD + d1);
            qhi[ks][0] = pack_bf16(x0.x, x0.y);
            qhi[ks][1] = pack_bf16(x1.x, x1.y);
            qhi[ks][2] = pack_bf16(x2.x, x2.y);
            qhi[ks][3] = pack_bf16(x3.x, x3.y);
            qlo[ks][0] = pack_bf16(x0.x - bf_hi(qhi[ks][0]), x0.y - bf_lo(qhi[ks][0]));
            qlo[ks][1] = pack_bf16(x1.x - bf_hi(qhi[ks][1]), x1.y - bf_lo(qhi[ks][1]));
            qlo[ks][2] = pack_bf16(x2.x - bf_hi(qhi[ks][2]), x2.y - bf_lo(qhi[ks][2]));
            qlo[ks][3] = pack_bf16(x3.x - bf_hi(qhi[ks][3]), x3.y - bf_lo(qhi[ks][3]));
        }
        __syncthreads();   // Qtmp region free before cp.async writes
    }

    const int qrow0 = q0 + wr * 16 + g;
    const int qrow8 = qrow0 + 8;
    const uint32_t* mb0 = g_mbits + ((size_t)b * SS + qrow0) * (SS / 32);
    const uint32_t* mb8 = g_mbits + ((size_t)b * SS + qrow8) * (SS / 32);
    float* arow0 = attn + ((size_t)bh * SS + qrow0) * SS;
    float* arow8 = attn + ((size_t)bh * SS + qrow8) * SS;

    // V frag (ldmatrix trans) per-lane offset within a part
    const int lkey = lane & 15;
    const uint32_t vfrag_off = ((wc * 32 + lkey) * KST) * 2;
    // K frag (ldmatrix non-trans) per-lane offset within a part
    const uint32_t kfrag_off =
        (((wc * 32 + (lane >> 4) * 8 + (lane & 7)) * KST) + ((lane >> 3) & 1) * 8) * 2;

    // ---- prologue: issue tiles 0 and 1 ----
    stage_async(sbase + 0 * BUF_B, kvbase + 0 * (size_t)KT * DD, tid);
    CP_COMMIT();
    stage_async(sbase + 1 * BUF_B, kvbase + 1 * (size_t)KT * DD, tid);
    CP_COMMIT();

    float O[8][4];
    #pragma unroll
    for (int i = 0; i < 8; ++i)
        #pragma unroll
        for (int c = 0; c < 4; ++c) O[i][c] = 0.0f;
    float Zp0 = 0.0f, Zp1 = 0.0f;

    int cur = 0;
    for (int t = 0; t < NTILES; ++t) {
        // prefetch this tile's mask bits (1 word covers this warp's 32 keys)
        uint32_t mw0 = mb0[2 * t + wc];
        uint32_t mw8 = mb8[2 * t + wc];

        if (t + 1 < NTILES) { CP_WAIT(1); } else { CP_WAIT(0); }
        __syncthreads();
        if (t + 2 < NTILES) {
            int nb = cur + 2; if (nb >= NBUF) nb -= NBUF;
            stage_async(sbase + nb * BUF_B, kvbase + (size_t)(t + 2) * KT * DD, tid);
            CP_COMMIT();
        }

        const uint32_t khi_b = sbase + cur * BUF_B + kfrag_off;
        const uint32_t klo_b = khi_b + TILE_B;
        const uint32_t vh_base = sbase + cur * BUF_B + 2 * TILE_B + vfrag_off;

        // ---------------- QK^T : S[4 n8][4] over 32 keys ----------------
        float S[4][4];
        #pragma unroll
        for (int i = 0; i < 4; ++i)
            #pragma unroll
            for (int c = 0; c < 4; ++c) S[i][c] = 0.0f;

        #pragma unroll
        for (int ks = 0; ks < 4; ++ks) {
            uint32_t bh0[4], bh1[4], bl0[4], bl1[4];
            ldsm_x4(bh0[0], bh1[0], bh0[1], bh1[1], khi_b + ks * 32);
            ldsm_x4(bh0[2], bh1[2], bh0[3], bh1[3], khi_b + ks * 32 + 16 * KST * 2);
            ldsm_x4(bl0[0], bl1[0], bl0[1], bl1[1], klo_b + ks * 32);
            ldsm_x4(bl0[2], bl1[2], bl0[3], bl1[3], klo_b + ks * 32 + 16 * KST * 2);
            #pragma unroll
            for (int n8 = 0; n8 < 4; ++n8) mma16816(S[n8], qhi[ks], bh0[n8], bh1[n8]);
            #pragma unroll
            for (int n8 = 0; n8 < 4; ++n8) mma16816(S[n8], qlo[ks], bh0[n8], bh1[n8]);
            #pragma unroll
            for (int n8 = 0; n8 < 4; ++n8) mma16816(S[n8], qhi[ks], bl0[n8], bl1[n8]);
        }

        // ---------------- mask + exp + attn store + Z + P frags (fp16) ---------
        uint32_t phi[2][4];
        #pragma unroll
        for (int gi = 0; gi < 4; ++gi) {
            int cb = t * KT + wc * 32 + gi * 8 + j2;
            int bit = gi * 8 + j2;
            float e0 = ((mw0 >> bit) & 1)       ? fexp2f(fmaf(S[gi][0], L2E, -SHL2)) : 0.0f;
            float e1 = ((mw0 >> (bit + 1)) & 1) ? fexp2f(fmaf(S[gi][1], L2E, -SHL2)) : 0.0f;
            float e2 = ((mw8 >> bit) & 1)       ? fexp2f(fmaf(S[gi][2], L2E, -SHL2)) : 0.0f;
            float e3 = ((mw8 >> (bit + 1)) & 1) ? fexp2f(fmaf(S[gi][3], L2E, -SHL2)) : 0.0f;
            *(float2*)(arow0 + cb) = make_float2(e0, e1);
            *(float2*)(arow8 + cb) = make_float2(e2, e3);
            Zp0 += e0 + e1;
            Zp1 += e2 + e3;
            int kc = gi >> 1, hh = (gi & 1) << 1;
            phi[kc][hh + 0] = pack_f16(e0, e1);
            phi[kc][hh + 1] = pack_f16(e2, e3);
        }

        // ---------------- P @ V (fp16 x fp16) : O[8 dn8][4] ----------------
        #pragma unroll
        for (int kc = 0; kc < 2; ++kc) {
            #pragma unroll
            for (int dn8 = 0; dn8 < 8; ++dn8) {
                uint32_t vh0, vh1;
                ldsm_x2_trans(vh0, vh1, vh_base + (kc * 16 * KST + dn8 * 8) * 2);
                mma16816h(O[dn8], phi[kc], vh0, vh1);
            }
        }

        if (++cur == NBUF) cur = 0;
    }

    // ---------------- epilogue: Z reduce ----------------
    Zp0 += __shfl_xor_sync(0xffffffffu, Zp0, 1);
    Zp0 += __shfl_xor_sync(0xffffffffu, Zp0, 2);
    Zp1 += __shfl_xor_sync(0xffffffffu, Zp1, 1);
    Zp1 += __shfl_xor_sync(0xffffffffu, Zp1, 2);
    __syncthreads();              // all tiles done using smem; attn writes visible
    if ((lane & 3) == 0) {
        Zbuf[wc * TM + wr * 16 + g]     = Zp0;
        Zbuf[wc * TM + wr * 16 + g + 8] = Zp1;
    }
    __syncthreads();
    if (tid < TM) {
        invZs[tid] = 1.0f / (Zbuf[tid] + Zbuf[TM + tid]);
    }

    // ---------------- O reduce + write out ----------------
    float* Obuf = (float*)dsm;    // [64][68] f32 = 17408 B
    const int r0 = wr * 16 + g, r1 = r0 + 8;
    if (wc == 0) {
        #pragma unroll
        for (int dn8 = 0; dn8 < 8; ++dn8) {
            *(float2*)(Obuf + r0 * 68 + dn8 * 8 + j2) = make_float2(O[dn8][0], O[dn8][1]);
            *(float2*)(Obuf + r1 * 68 + dn8 * 8 + j2) = make_float2(O[dn8][2], O[dn8][3]);
        }
    }
    __syncthreads();
    if (wc == 1) {
        #pragma unroll
        for (int dn8 = 0; dn8 < 8; ++dn8) {
            float2* p0 = (float2*)(Obuf + r0 * 68 + dn8 * 8 + j2);
            float2* p1 = (float2*)(Obuf + r1 * 68 + dn8 * 8 + j2);
            float2 a0 = *p0, a1 = *p1;
            a0.x += O[dn8][0]; a0.y += O[dn8][1];
            a1.x += O[dn8][2]; a1.y += O[dn8][3];
            *p0 = a0; *p1 = a1;
        }
    }
    __syncthreads();
    {
        int row = tid >> 2;
        int dq  = (tid & 3) * 16;
        float iz = invZs[row];
        float* orow = out + ((size_t)bh * SS + q0 + row) * DD + dq;
        #pragma unroll
        for (int i = 0; i < 4; ++i) {
            float4 x = *(float4*)(Obuf + row * 68 + dq + i * 4);
            x.x *= iz; x.y *= iz; x.z *= iz; x.w *= iz;
            *(float4*)(orow + i * 4) = x;
        }
    }

    // ---------------- fused attn normalization ----------------
    {
        float* attn_base = attn + ((size_t)bh * SS + q0) * SS;
        #pragma unroll
        for (int rr = 0; rr < 8; ++rr) {
            int row = w + 8 * rr;
            float iz = invZs[row];
            float4* a4 = (float4*)(attn_base + (size_t)row * SS);
            #pragma unroll 4
            for (int i = 0; i < 16; ++i) {
                int idx = lane + 32 * i;
                float4 x = a4[idx];
                x.x *= iz; x.y *= iz; x.z *= iz; x.w *= iz;
                a4[idx] = x;
            }
        }
    }
}

extern "C" void kernel_launch(void* const* d_in, const int* in_sizes, int n_in,
                              void* d_out, int out_size)
{
    const float* q    = (const float*)d_in[0];
    const float* k    = (const float*)d_in[1];
    const float* v    = (const float*)d_in[2];
    const int*   mask = (const int*)d_in[3];

    float* out  = (float*)d_out;
    float* attn = out + (size_t)BB * HH * SS * DD;

    static bool configured = false;
    if (!configured) {
        cudaFuncSetAttribute(psdpa_mma_kernel,
                             cudaFuncAttributeMaxDynamicSharedMemorySize, SMEM_TOTAL);
        configured = true;
    }

    prepack_kernel<<<NELEM / 4 / 256, 256>>>(k, v);
    maskpack_kernel<<<(BB * SS * SS) / 256, 256>>>(mask);

    dim3 grid1(SS / TM, BB * HH);
    psdpa_mma_kernel<<<grid1, NTHREADS, SMEM_TOTAL>>>(q, out, attn);
}

// round 11
// speedup vs baseline: 2.3925x; 1.1495x over previous
#include <cuda_runtime.h>
#include <cuda_bf16.h>
#include <cuda_fp16.h>
#include <cstdint>

#define BB 4
#define HH 16
#define SS 2048
#define DD 64

#define TM 64          // q rows per CTA
#define KT 64          // keys per tile
#define NTILES (SS / KT)
#define NTHREADS 256
#define KST 72         // smem row stride in halves (144B): conflict-free frag loads

#define TILE_B  (KT * KST * 2)     // 9216 bytes per part
#define NPART 2                    // Kh, Vh (both fp16)
#define BUF_B   (NPART * TILE_B)   // 18432
#define NBUF 3
#define ZBUF_OFF (NBUF * BUF_B)    // 55296
#define INVZ_OFF (ZBUF_OFF + 512)
#define SMEM_TOTAL (INVZ_OFF + 256)

#define NELEM (BB * HH * SS * DD)  // 8388608
#define MWORDS (BB * SS * (SS / 32))  // 524288 uint32

__device__ uint16_t g_kh[NELEM];
__device__ uint16_t g_vh[NELEM];
__device__ uint32_t g_mbits[MWORDS];

// ---------------- fast 2^y (FFMA only, deg-4), rel err ~3e-5 ----------------
__device__ __forceinline__ float fexp2f(float y) {
    float t = y + 12582912.0f;               // round-to-int via 1.5*2^23
    int   i = __float_as_int(t) << 23;
    float f = y - (t - 12582912.0f);
    float r = 9.6715857e-3f;
    r = fmaf(r, f, 5.5503714e-2f);
    r = fmaf(r, f, 2.4015310e-1f);
    r = fmaf(r, f, 6.9315315e-1f);
    r = fmaf(r, f, 1.0f);
    return __int_as_float(__float_as_int(r) + i);
}
#define L2E  1.4426950408889634f
#define SHL2 11.541560327111707f   // 8*log2(e):  exp(s-8) = 2^(s*L2E - SHL2)

// ---------------- wrappers ----------------
__device__ __forceinline__ void mma16816h(float* c, const uint32_t* a, uint32_t b0, uint32_t b1) {
    asm volatile(
        "mma.sync.aligned.m16n8k16.row.col.f32.f16.f16.f32 "
        "{%0,%1,%2,%3},{%4,%5,%6,%7},{%8,%9},{%0,%1,%2,%3};"
        : "+f"(c[0]), "+f"(c[1]), "+f"(c[2]), "+f"(c[3])
        : "r"(a[0]), "r"(a[1]), "r"(a[2]), "r"(a[3]), "r"(b0), "r"(b1));
}
__device__ __forceinline__ void ldsm_x2_trans(uint32_t& r0, uint32_t& r1, uint32_t addr) {
    asm volatile("ldmatrix.sync.aligned.m8n8.x2.trans.shared.b16 {%0,%1}, [%2];"
                 : "=r"(r0), "=r"(r1) : "r"(addr));
}
__device__ __forceinline__ void ldsm_x4(uint32_t& r0, uint32_t& r1, uint32_t& r2, uint32_t& r3,
                                        uint32_t addr) {
    asm volatile("ldmatrix.sync.aligned.m8n8.x4.shared.b16 {%0,%1,%2,%3}, [%4];"
                 : "=r"(r0), "=r"(r1), "=r"(r2), "=r"(r3) : "r"(addr));
}
__device__ __forceinline__ uint32_t pack_f16(float x, float y) {
    __half2 h = __floats2half2_rn(x, y);
    return *(uint32_t*)&h;
}

__device__ __forceinline__ void cp16(uint32_t dst, const void* src) {
    asm volatile("cp.async.cg.shared.global [%0], [%1], 16;" :: "r"(dst), "l"(src));
}
#define CP_COMMIT() asm volatile("cp.async.commit_group;" ::: "memory")
#define CP_WAIT(n)  asm volatile("cp.async.wait_group %0;" :: "n"(n) : "memory")

// stage one tile (2 parts) via cp.async: 4 x 16B per thread
__device__ __forceinline__ void stage_async(uint32_t sbuf, size_t base, int tid) {
    const uint16_t* srcs[NPART] = {g_kh + base, g_vh + base};
    #pragma unroll
    for (int part = 0; part < NPART; ++part) {
        uint32_t dpart = sbuf + part * TILE_B;
        #pragma unroll
        for (int it = 0; it < 2; ++it) {
            int idx = tid + it * NTHREADS;     // 0..511
            int row = idx >> 3;
            int seg = idx & 7;
            cp16(dpart + row * 144 + seg * 16, srcs[part] + row * 64 + seg * 8);
        }
    }
}

// ---------------- prepack: f32 K,V -> fp16 ----------------
__global__ __launch_bounds__(256)
void prepack_kernel(const float* __restrict__ k, const float* __restrict__ v)
{
    size_t i = (size_t)blockIdx.x * 256 + threadIdx.x;   // float4 index
    float4 x = ((const float4*)k)[i];
    ((uint2*)g_kh)[i] = make_uint2(pack_f16(x.x, x.y), pack_f16(x.z, x.w));
    float4 y = ((const float4*)v)[i];
    ((uint2*)g_vh)[i] = make_uint2(pack_f16(y.x, y.y), pack_f16(y.z, y.w));
}

// ---------------- maskpack: int32 mask -> bitmask ----------------
__global__ __launch_bounds__(256)
void maskpack_kernel(const int* __restrict__ mask)
{
    size_t i = (size_t)blockIdx.x * 256 + threadIdx.x;
    int m = mask[i];
    uint32_t bits = __ballot_sync(0xffffffffu, m != 0);
    if ((threadIdx.x & 31) == 0) g_mbits[i >> 5] = bits;
}

__global__ __launch_bounds__(NTHREADS, 2)
void psdpa_mma_kernel(const float* __restrict__ q,
                      float* __restrict__ out,
                      float* __restrict__ attn)
{
    extern __shared__ __align__(16) char dsm[];
    float* Zbuf  = (float*)(dsm + ZBUF_OFF);
    float* invZs = (float*)(dsm + INVZ_OFF);
    const uint32_t sbase = (uint32_t)__cvta_generic_to_shared(dsm);

    const int tid  = threadIdx.x;
    const int w    = tid >> 5;
    const int lane = tid & 31;
    const int wr   = w & 3;        // row group (16 rows each)
    const int wc   = w >> 2;       // key-column half (32 keys each)
    const int g    = lane >> 2;
    const int j2   = (lane & 3) << 1;

    const int bh = blockIdx.y;
    const int b  = bh >> 4;
    const int q0 = blockIdx.x * TM;

    const float* qbase = q + ((size_t)bh * SS + q0) * DD;
    const size_t kvbase = (size_t)bh * SS * DD;

    // ---- Q fragments (scaled 1/8), fp16; f32 staging in buffer region ----
    uint32_t qh[4][4];
    {
        float* Qtmp = (float*)dsm;   // 16 KB
        const float4* qg = (const float4*)qbase;
        #pragma unroll
        for (int it = 0; it < 4; ++it) {
            int idx = tid + it * NTHREADS;
            int row = idx >> 4;
            int d4  = (idx & 15) << 2;
            float4 x = qg[idx];
            x.x *= 0.125f; x.y *= 0.125f; x.z *= 0.125f; x.w *= 0.125f;
            *(float4*)(Qtmp + row * DD + d4) = x;
        }
        __syncthreads();
        const int r0 = wr * 16 + g, r1 = r0 + 8;
        #pragma unroll
        for (int ks = 0; ks < 4; ++ks) {
            int d0 = ks * 16 + j2, d1 = d0 + 8;
            float2 x0 = *(float2*)(Qtmp + r0 * DD + d0);
            float2 x1 = *(float2*)(Qtmp + r1 * DD + d0);
            float2 x2 = *(float2*)(Qtmp + r0 * DD + d1);
            float2 x3 = *(float2*)(Qtmp + r1 * DD + d1);
            qh[ks][0] = pack_f16(x0.x, x0.y);
            qh[ks][1] = pack_f16(x1.x, x1.y);
            qh[ks][2] = pack_f16(x2.x, x2.y);
            qh[ks][3] = pack_f16(x3.x, x3.y);
        }
        __syncthreads();   // Qtmp region free before cp.async writes
    }

    const int qrow0 = q0 + wr * 16 + g;
    const int qrow8 = qrow0 + 8;
    const uint32_t* mb0 = g_mbits + ((size_t)b * SS + qrow0) * (SS / 32);
    const uint32_t* mb8 = g_mbits + ((size_t)b * SS + qrow8) * (SS / 32);
    float* arow0 = attn + ((size_t)bh * SS + qrow0) * SS;
    float* arow8 = attn + ((size_t)bh * SS + qrow8) * SS;

    // V frag (ldmatrix trans) per-lane offset within a part
    const int lkey = lane & 15;
    const uint32_t vfrag_off = ((wc * 32 + lkey) * KST) * 2;
    // K frag (ldmatrix non-trans) per-lane offset within a part
    const uint32_t kfrag_off =
        (((wc * 32 + (lane >> 4) * 8 + (lane & 7)) * KST) + ((lane >> 3) & 1) * 8) * 2;

    // ---- prologue: issue tiles 0 and 1 ----
    stage_async(sbase + 0 * BUF_B, kvbase + 0 * (size_t)KT * DD, tid);
    CP_COMMIT();
    stage_async(sbase + 1 * BUF_B, kvbase + 1 * (size_t)KT * DD, tid);
    CP_COMMIT();

    float O[8][4];
    #pragma unroll
    for (int i = 0; i < 8; ++i)
        #pragma unroll
        for (int c = 0; c < 4; ++c) O[i][c] = 0.0f;
    float Zp0 = 0.0f, Zp1 = 0.0f;

    int cur = 0;
    for (int t = 0; t < NTILES; ++t) {
        // prefetch this tile's mask bits (1 word covers this warp's 32 keys)
        uint32_t mw0 = mb0[2 * t + wc];
        uint32_t mw8 = mb8[2 * t + wc];

        if (t + 1 < NTILES) { CP_WAIT(1); } else { CP_WAIT(0); }
        __syncthreads();
        if (t + 2 < NTILES) {
            int nb = cur + 2; if (nb >= NBUF) nb -= NBUF;
            stage_async(sbase + nb * BUF_B, kvbase + (size_t)(t + 2) * KT * DD, tid);
            CP_COMMIT();
        }

        const uint32_t kh_b = sbase + cur * BUF_B + kfrag_off;
        const uint32_t vh_base = sbase + cur * BUF_B + TILE_B + vfrag_off;

        // ---------------- QK^T (fp16) : S[4 n8][4] over 32 keys ----------------
        float S[4][4];
        #pragma unroll
        for (int i = 0; i < 4; ++i)
            #pragma unroll
            for (int c = 0; c < 4; ++c) S[i][c] = 0.0f;

        #pragma unroll
        for (int ks = 0; ks < 4; ++ks) {
            uint32_t bh0[4], bh1[4];
            ldsm_x4(bh0[0], bh1[0], bh0[1], bh1[1], kh_b + ks * 32);
            ldsm_x4(bh0[2], bh1[2], bh0[3], bh1[3], kh_b + ks * 32 + 16 * KST * 2);
            #pragma unroll
            for (int n8 = 0; n8 < 4; ++n8) mma16816h(S[n8], qh[ks], bh0[n8], bh1[n8]);
        }

        // ---------------- mask + exp + attn store + Z + P frags (fp16) ---------
        uint32_t phi[2][4];
        #pragma unroll
        for (int gi = 0; gi < 4; ++gi) {
            int cb = t * KT + wc * 32 + gi * 8 + j2;
            int bit = gi * 8 + j2;
            float e0 = ((mw0 >> bit) & 1)       ? fexp2f(fmaf(S[gi][0], L2E, -SHL2)) : 0.0f;
            float e1 = ((mw0 >> (bit + 1)) & 1) ? fexp2f(fmaf(S[gi][1], L2E, -SHL2)) : 0.0f;
            float e2 = ((mw8 >> bit) & 1)       ? fexp2f(fmaf(S[gi][2], L2E, -SHL2)) : 0.0f;
            float e3 = ((mw8 >> (bit + 1)) & 1) ? fexp2f(fmaf(S[gi][3], L2E, -SHL2)) : 0.0f;
            *(float2*)(arow0 + cb) = make_float2(e0, e1);
            *(float2*)(arow8 + cb) = make_float2(e2, e3);
            Zp0 += e0 + e1;
            Zp1 += e2 + e3;
            int kc = gi >> 1, hh = (gi & 1) << 1;
            phi[kc][hh + 0] = pack_f16(e0, e1);
            phi[kc][hh + 1] = pack_f16(e2, e3);
        }

        // ---------------- P @ V (fp16 x fp16) : O[8 dn8][4] ----------------
        #pragma unroll
        for (int kc = 0; kc < 2; ++kc) {
            #pragma unroll
            for (int dn8 = 0; dn8 < 8; ++dn8) {
                uint32_t vh0, vh1;
                ldsm_x2_trans(vh0, vh1, vh_base + (kc * 16 * KST + dn8 * 8) * 2);
                mma16816h(O[dn8], phi[kc], vh0, vh1);
            }
        }

        if (++cur == NBUF) cur = 0;
    }

    // ---------------- epilogue: Z reduce ----------------
    Zp0 += __shfl_xor_sync(0xffffffffu, Zp0, 1);
    Zp0 += __shfl_xor_sync(0xffffffffu, Zp0, 2);
    Zp1 += __shfl_xor_sync(0xffffffffu, Zp1, 1);
    Zp1 += __shfl_xor_sync(0xffffffffu, Zp1, 2);
    __syncthreads();              // all tiles done using smem; attn writes visible
    if ((lane & 3) == 0) {
        Zbuf[wc * TM + wr * 16 + g]     = Zp0;
        Zbuf[wc * TM + wr * 16 + g + 8] = Zp1;
    }
    __syncthreads();
    if (tid < TM) {
        invZs[tid] = 1.0f / (Zbuf[tid] + Zbuf[TM + tid]);
    }

    // ---------------- O reduce + write out ----------------
    float* Obuf = (float*)dsm;    // [64][68] f32 = 17408 B
    const int r0 = wr * 16 + g, r1 = r0 + 8;
    if (wc == 0) {
        #pragma unroll
        for (int dn8 = 0; dn8 < 8; ++dn8) {
            *(float2*)(Obuf + r0 * 68 + dn8 * 8 + j2) = make_float2(O[dn8][0], O[dn8][1]);
            *(float2*)(Obuf + r1 * 68 + dn8 * 8 + j2) = make_float2(O[dn8][2], O[dn8][3]);
        }
    }
    __syncthreads();
    if (wc == 1) {
        #pragma unroll
        for (int dn8 = 0; dn8 < 8; ++dn8) {
            float2* p0 = (float2*)(Obuf + r0 * 68 + dn8 * 8 + j2);
            float2* p1 = (float2*)(Obuf + r1 * 68 + dn8 * 8 + j2);
            float2 a0 = *p0, a1 = *p1;
            a0.x += O[dn8][0]; a0.y += O[dn8][1];
            a1.x += O[dn8][2]; a1.y += O[dn8][3];
            *p0 = a0; *p1 = a1;
        }
    }
    __syncthreads();
    {
        int row = tid >> 2;
        int dq  = (tid & 3) * 16;
        float iz = invZs[row];
        float* orow = out + ((size_t)bh * SS + q0 + row) * DD + dq;
        #pragma unroll
        for (int i = 0; i < 4; ++i) {
            float4 x = *(float4*)(Obuf + row * 68 + dq + i * 4);
            x.x *= iz; x.y *= iz; x.z *= iz; x.w *= iz;
            *(float4*)(orow + i * 4) = x;
        }
    }

    // ---------------- fused attn normalization ----------------
    {
        float* attn_base = attn + ((size_t)bh * SS + q0) * SS;
        #pragma unroll
        for (int rr = 0; rr < 8; ++rr) {
            int row = w + 8 * rr;
            float iz = invZs[row];
            float4* a4 = (float4*)(attn_base + (size_t)row * SS);
            #pragma unroll 4
            for (int i = 0; i < 16; ++i) {
                int idx = lane + 32 * i;
                float4 x = a4[idx];
                x.x *= iz; x.y *= iz; x.z *= iz; x.w *= iz;
                a4[idx] = x;
            }
        }
    }
}

extern "C" void kernel_launch(void* const* d_in, const int* in_sizes, int n_in,
                              void* d_out, int out_size)
{
    const float* q    = (const float*)d_in[0];
    const float* k    = (const float*)d_in[1];
    const float* v    = (const float*)d_in[2];
    const int*   mask = (const int*)d_in[3];

    float* out  = (float*)d_out;
    float* attn = out + (size_t)BB * HH * SS * DD;

    static bool configured = false;
    if (!configured) {
        cudaFuncSetAttribute(psdpa_mma_kernel,
                             cudaFuncAttributeMaxDynamicSharedMemorySize, SMEM_TOTAL);
        configured = true;
    }

    prepack_kernel<<<NELEM / 4 / 256, 256>>>(k, v);
    maskpack_kernel<<<(BB * SS * SS) / 256, 256>>>(mask);

    dim3 grid1(SS / TM, BB * HH);
    psdpa_mma_kernel<<<grid1, NTHREADS, SMEM_TOTAL>>>(q, out, attn);
}

// round 12
// speedup vs baseline: 2.6963x; 1.1270x over previous
#include <cuda_runtime.h>
#include <cuda_bf16.h>
#include <cuda_fp16.h>
#include <cstdint>

#define BB 4
#define HH 16
#define SS 2048
#define DD 64

#define TM 64          // q rows per CTA
#define KT 64          // keys per tile
#define NTILES (SS / KT)
#define NTHREADS 256
#define KST 72         // smem row stride in halves (144B): conflict-free frag loads

#define TILE_B  (KT * KST * 2)     // 9216 bytes per part
#define NPART 2                    // Kh, Vh (both fp16)
#define BUF_B   (NPART * TILE_B)   // 18432
#define NBUF 3
#define ZBUF_OFF (NBUF * BUF_B)    // 55296
#define INVZ_OFF (ZBUF_OFF + 512)
#define SMEM_TOTAL (INVZ_OFF + 256)

#define NELEM (BB * HH * SS * DD)  // 8388608
#define MWORDS (BB * SS * (SS / 32))  // 524288 uint32

__device__ uint16_t g_kh[NELEM];
__device__ uint16_t g_vh[NELEM];
__device__ uint32_t g_mbits[MWORDS];

// ---------------- fast 2^y via MUFU.EX2 (1 instr) ----------------
__device__ __forceinline__ float fexp2f(float y) {
    float r;
    asm("ex2.approx.f32 %0, %1;" : "=f"(r) : "f"(y));
    return r;
}
#define L2E  1.4426950408889634f
#define SHL2 11.541560327111707f   // 8*log2(e):  exp(s-8) = 2^(s*L2E - SHL2)

// ---------------- wrappers ----------------
__device__ __forceinline__ void mma16816h(float* c, const uint32_t* a, uint32_t b0, uint32_t b1) {
    asm volatile(
        "mma.sync.aligned.m16n8k16.row.col.f32.f16.f16.f32 "
        "{%0,%1,%2,%3},{%4,%5,%6,%7},{%8,%9},{%0,%1,%2,%3};"
        : "+f"(c[0]), "+f"(c[1]), "+f"(c[2]), "+f"(c[3])
        : "r"(a[0]), "r"(a[1]), "r"(a[2]), "r"(a[3]), "r"(b0), "r"(b1));
}
__device__ __forceinline__ void ldsm_x2_trans(uint32_t& r0, uint32_t& r1, uint32_t addr) {
    asm volatile("ldmatrix.sync.aligned.m8n8.x2.trans.shared.b16 {%0,%1}, [%2];"
                 : "=r"(r0), "=r"(r1) : "r"(addr));
}
__device__ __forceinline__ void ldsm_x4(uint32_t& r0, uint32_t& r1, uint32_t& r2, uint32_t& r3,
                                        uint32_t addr) {
    asm volatile("ldmatrix.sync.aligned.m8n8.x4.shared.b16 {%0,%1,%2,%3}, [%4];"
                 : "=r"(r0), "=r"(r1), "=r"(r2), "=r"(r3) : "r"(addr));
}
__device__ __forceinline__ uint32_t pack_f16(float x, float y) {
    __half2 h = __floats2half2_rn(x, y);
    return *(uint32_t*)&h;
}

__device__ __forceinline__ void cp16(uint32_t dst, const void* src) {
    asm volatile("cp.async.cg.shared.global [%0], [%1], 16;" :: "r"(dst), "l"(src));
}
#define CP_COMMIT() asm volatile("cp.async.commit_group;" ::: "memory")
#define CP_WAIT(n)  asm volatile("cp.async.wait_group %0;" :: "n"(n) : "memory")

// stage one tile (2 parts) via cp.async: 4 x 16B per thread
__device__ __forceinline__ void stage_async(uint32_t sbuf, size_t base, int tid) {
    const uint16_t* srcs[NPART] = {g_kh + base, g_vh + base};
    #pragma unroll
    for (int part = 0; part < NPART; ++part) {
        uint32_t dpart = sbuf + part * TILE_B;
        #pragma unroll
        for (int it = 0; it < 2; ++it) {
            int idx = tid + it * NTHREADS;     // 0..511
            int row = idx >> 3;
            int seg = idx & 7;
            cp16(dpart + row * 144 + seg * 16, srcs[part] + row * 64 + seg * 8);
        }
    }
}

// ---------------- prepack: f32 K,V -> fp16 ----------------
__global__ __launch_bounds__(256)
void prepack_kernel(const float* __restrict__ k, const float* __restrict__ v)
{
    size_t i = (size_t)blockIdx.x * 256 + threadIdx.x;   // float4 index
    float4 x = ((const float4*)k)[i];
    ((uint2*)g_kh)[i] = make_uint2(pack_f16(x.x, x.y), pack_f16(x.z, x.w));
    float4 y = ((const float4*)v)[i];
    ((uint2*)g_vh)[i] = make_uint2(pack_f16(y.x, y.y), pack_f16(y.z, y.w));
}

// ---------------- maskpack: int32 mask -> bitmask ----------------
__global__ __launch_bounds__(256)
void maskpack_kernel(const int* __restrict__ mask)
{
    size_t i = (size_t)blockIdx.x * 256 + threadIdx.x;
    int m = mask[i];
    uint32_t bits = __ballot_sync(0xffffffffu, m != 0);
    if ((threadIdx.x & 31) == 0) g_mbits[i >> 5] = bits;
}

__global__ __launch_bounds__(NTHREADS, 2)
void psdpa_mma_kernel(const float* __restrict__ q,
                      float* __restrict__ out,
                      float* __restrict__ attn)
{
    extern __shared__ __align__(16) char dsm[];
    float* Zbuf  = (float*)(dsm + ZBUF_OFF);
    float* invZs = (float*)(dsm + INVZ_OFF);
    const uint32_t sbase = (uint32_t)__cvta_generic_to_shared(dsm);

    const int tid  = threadIdx.x;
    const int w    = tid >> 5;
    const int lane = tid & 31;
    const int wr   = w & 3;        // row group (16 rows each)
    const int wc   = w >> 2;       // key-column half (32 keys each)
    const int g    = lane >> 2;
    const int j2   = (lane & 3) << 1;

    const int bh = blockIdx.y;
    const int b  = bh >> 4;
    const int q0 = blockIdx.x * TM;

    const float* qbase = q + ((size_t)bh * SS + q0) * DD;
    const size_t kvbase = (size_t)bh * SS * DD;

    // ---- Q fragments (scaled 1/8), fp16; f32 staging in buffer region ----
    uint32_t qh[4][4];
    {
        float* Qtmp = (float*)dsm;   // 16 KB
        const float4* qg = (const float4*)qbase;
        #pragma unroll
        for (int it = 0; it < 4; ++it) {
            int idx = tid + it * NTHREADS;
            int row = idx >> 4;
            int d4  = (idx & 15) << 2;
            float4 x = qg[idx];
            x.x *= 0.125f; x.y *= 0.125f; x.z *= 0.125f; x.w *= 0.125f;
            *(float4*)(Qtmp + row * DD + d4) = x;
        }
        __syncthreads();
        const int r0 = wr * 16 + g, r1 = r0 + 8;
        #pragma unroll
        for (int ks = 0; ks < 4; ++ks) {
            int d0 = ks * 16 + j2, d1 = d0 + 8;
            float2 x0 = *(float2*)(Qtmp + r0 * DD + d0);
            float2 x1 = *(float2*)(Qtmp + r1 * DD + d0);
            float2 x2 = *(float2*)(Qtmp + r0 * DD + d1);
            float2 x3 = *(float2*)(Qtmp + r1 * DD + d1);
            qh[ks][0] = pack_f16(x0.x, x0.y);
            qh[ks][1] = pack_f16(x1.x, x1.y);
            qh[ks][2] = pack_f16(x2.x, x2.y);
            qh[ks][3] = pack_f16(x3.x, x3.y);
        }
        __syncthreads();   // Qtmp region free before cp.async writes
    }

    const int qrow0 = q0 + wr * 16 + g;
    const int qrow8 = qrow0 + 8;
    const uint32_t* mb0 = g_mbits + ((size_t)b * SS + qrow0) * (SS / 32);
    const uint32_t* mb8 = g_mbits + ((size_t)b * SS + qrow8) * (SS / 32);
    float* arow0 = attn + ((size_t)bh * SS + qrow0) * SS;
    float* arow8 = attn + ((size_t)bh * SS + qrow8) * SS;

    // V frag (ldmatrix trans) per-lane offset within a part
    const int lkey = lane & 15;
    const uint32_t vfrag_off = ((wc * 32 + lkey) * KST) * 2;
    // K frag (ldmatrix non-trans) per-lane offset within a part
    const uint32_t kfrag_off =
        (((wc * 32 + (lane >> 4) * 8 + (lane & 7)) * KST) + ((lane >> 3) & 1) * 8) * 2;

    // ---- prologue: issue tiles 0 and 1 ----
    stage_async(sbase + 0 * BUF_B, kvbase + 0 * (size_t)KT * DD, tid);
    CP_COMMIT();
    stage_async(sbase + 1 * BUF_B, kvbase + 1 * (size_t)KT * DD, tid);
    CP_COMMIT();

    float O[8][4];
    #pragma unroll
    for (int i = 0; i < 8; ++i)
        #pragma unroll
        for (int c = 0; c < 4; ++c) O[i][c] = 0.0f;
    float Zp0 = 0.0f, Zp1 = 0.0f;

    int cur = 0;
    for (int t = 0; t < NTILES; ++t) {
        // prefetch this tile's mask bits (1 word covers this warp's 32 keys)
        uint32_t mw0 = mb0[2 * t + wc];
        uint32_t mw8 = mb8[2 * t + wc];

        if (t + 1 < NTILES) { CP_WAIT(1); } else { CP_WAIT(0); }
        __syncthreads();
        if (t + 2 < NTILES) {
            int nb = cur + 2; if (nb >= NBUF) nb -= NBUF;
            stage_async(sbase + nb * BUF_B, kvbase + (size_t)(t + 2) * KT * DD, tid);
            CP_COMMIT();
        }

        const uint32_t kh_b = sbase + cur * BUF_B + kfrag_off;
        const uint32_t vh_base = sbase + cur * BUF_B + TILE_B + vfrag_off;

        // ---------------- QK^T (fp16) : S[4 n8][4] over 32 keys ----------------
        float S[4][4];
        #pragma unroll
        for (int i = 0; i < 4; ++i)
            #pragma unroll
            for (int c = 0; c < 4; ++c) S[i][c] = 0.0f;

        #pragma unroll
        for (int ks = 0; ks < 4; ++ks) {
            uint32_t bh0[4], bh1[4];
            ldsm_x4(bh0[0], bh1[0], bh0[1], bh1[1], kh_b + ks * 32);
            ldsm_x4(bh0[2], bh1[2], bh0[3], bh1[3], kh_b + ks * 32 + 16 * KST * 2);
            #pragma unroll
            for (int n8 = 0; n8 < 4; ++n8) mma16816h(S[n8], qh[ks], bh0[n8], bh1[n8]);
        }

        // ---------------- mask + exp (MUFU) + attn store + Z + P frags ---------
        uint32_t phi[2][4];
        #pragma unroll
        for (int gi = 0; gi < 4; ++gi) {
            int cb = t * KT + wc * 32 + gi * 8 + j2;
            int bit = gi * 8 + j2;
            float e0 = ((mw0 >> bit) & 1)       ? fexp2f(fmaf(S[gi][0], L2E, -SHL2)) : 0.0f;
            float e1 = ((mw0 >> (bit + 1)) & 1) ? fexp2f(fmaf(S[gi][1], L2E, -SHL2)) : 0.0f;
            float e2 = ((mw8 >> bit) & 1)       ? fexp2f(fmaf(S[gi][2], L2E, -SHL2)) : 0.0f;
            float e3 = ((mw8 >> (bit + 1)) & 1) ? fexp2f(fmaf(S[gi][3], L2E, -SHL2)) : 0.0f;
            *(float2*)(arow0 + cb) = make_float2(e0, e1);
            *(float2*)(arow8 + cb) = make_float2(e2, e3);
            Zp0 += e0 + e1;
            Zp1 += e2 + e3;
            int kc = gi >> 1, hh = (gi & 1) << 1;
            phi[kc][hh + 0] = pack_f16(e0, e1);
            phi[kc][hh + 1] = pack_f16(e2, e3);
        }

        // ---------------- P @ V (fp16 x fp16) : O[8 dn8][4] ----------------
        #pragma unroll
        for (int kc = 0; kc < 2; ++kc) {
            #pragma unroll
            for (int dn8 = 0; dn8 < 8; ++dn8) {
                uint32_t vh0, vh1;
                ldsm_x2_trans(vh0, vh1, vh_base + (kc * 16 * KST + dn8 * 8) * 2);
                mma16816h(O[dn8], phi[kc], vh0, vh1);
            }
        }

        if (++cur == NBUF) cur = 0;
    }

    // ---------------- epilogue: Z reduce ----------------
    Zp0 += __shfl_xor_sync(0xffffffffu, Zp0, 1);
    Zp0 += __shfl_xor_sync(0xffffffffu, Zp0, 2);
    Zp1 += __shfl_xor_sync(0xffffffffu, Zp1, 1);
    Zp1 += __shfl_xor_sync(0xffffffffu, Zp1, 2);
    __syncthreads();              // all tiles done using smem; attn writes visible
    if ((lane & 3) == 0) {
        Zbuf[wc * TM + wr * 16 + g]     = Zp0;
        Zbuf[wc * TM + wr * 16 + g + 8] = Zp1;
    }
    __syncthreads();
    if (tid < TM) {
        invZs[tid] = 1.0f / (Zbuf[tid] + Zbuf[TM + tid]);
    }

    // ---------------- O reduce + write out ----------------
    float* Obuf = (float*)dsm;    // [64][68] f32 = 17408 B
    const int r0 = wr * 16 + g, r1 = r0 + 8;
    if (wc == 0) {
        #pragma unroll
        for (int dn8 = 0; dn8 < 8; ++dn8) {
            *(float2*)(Obuf + r0 * 68 + dn8 * 8 + j2) = make_float2(O[dn8][0], O[dn8][1]);
            *(float2*)(Obuf + r1 * 68 + dn8 * 8 + j2) = make_float2(O[dn8][2], O[dn8][3]);
        }
    }
    __syncthreads();
    if (wc == 1) {
        #pragma unroll
        for (int dn8 = 0; dn8 < 8; ++dn8) {
            float2* p0 = (float2*)(Obuf + r0 * 68 + dn8 * 8 + j2);
            float2* p1 = (float2*)(Obuf + r1 * 68 + dn8 * 8 + j2);
            float2 a0 = *p0, a1 = *p1;
            a0.x += O[dn8][0]; a0.y += O[dn8][1];
            a1.x += O[dn8][2]; a1.y += O[dn8][3];
            *p0 = a0; *p1 = a1;
        }
    }
    __syncthreads();
    {
        int row = tid >> 2;
        int dq  = (tid & 3) * 16;
        float iz = invZs[row];
        float* orow = out + ((size_t)bh * SS + q0 + row) * DD + dq;
        #pragma unroll
        for (int i = 0; i < 4; ++i) {
            float4 x = *(float4*)(Obuf + row * 68 + dq + i * 4);
            x.x *= iz; x.y *= iz; x.z *= iz; x.w *= iz;
            *(float4*)(orow + i * 4) = x;
        }
    }

    // ---------------- fused attn normalization ----------------
    {
        float* attn_base = attn + ((size_t)bh * SS + q0) * SS;
        #pragma unroll
        for (int rr = 0; rr < 8; ++rr) {
            int row = w + 8 * rr;
            float iz = invZs[row];
            float4* a4 = (float4*)(attn_base + (size_t)row * SS);
            #pragma unroll 4
            for (int i = 0; i < 16; ++i) {
                int idx = lane + 32 * i;
                float4 x = a4[idx];
                x.x *= iz; x.y *= iz; x.z *= iz; x.w *= iz;
                a4[idx] = x;
            }
        }
    }
}

extern "C" void kernel_launch(void* const* d_in, const int* in_sizes, int n_in,
                              void* d_out, int out_size)
{
    const float* q    = (const float*)d_in[0];
    const float* k    = (const float*)d_in[1];
    const float* v    = (const float*)d_in[2];
    const int*   mask = (const int*)d_in[3];

    float* out  = (float*)d_out;
    float* attn = out + (size_t)BB * HH * SS * DD;

    static bool configured = false;
    if (!configured) {
        cudaFuncSetAttribute(psdpa_mma_kernel,
                             cudaFuncAttributeMaxDynamicSharedMemorySize, SMEM_TOTAL);
        configured = true;
    }

    prepack_kernel<<<NELEM / 4 / 256, 256>>>(k, v);
    maskpack_kernel<<<(BB * SS * SS) / 256, 256>>>(mask);

    dim3 grid1(SS / TM, BB * HH);
    psdpa_mma_kernel<<<grid1, NTHREADS, SMEM_TOTAL>>>(q, out, attn);
}